// round 7
// baseline (speedup 1.0000x reference)
#include <cuda_runtime.h>
#include <math.h>
#include <stdint.h>

#define T_STEPS 256
#define BATCH   128
#define DIM     128
#define HID     1024
#define G4      4096      // 4*HID
#define NT      32        // tiles per layer (HID/NH)
#define NH      32        // hidden units per tile -> 128 z columns
#define KS      4         // split-K factor
#define NBLK    128       // persistent blocks = KS*NT
#define NTHR    256

// ---------------- device scratch ----------------------------------------------
__device__ __align__(16) float g_h2all[(size_t)T_STEPS * BATCH * HID];
__device__ __align__(16) float g_logits[(size_t)T_STEPS * BATCH * DIM];
__device__ __align__(16) float g_zpart[(size_t)KS * NT * BATCH * 128];
__device__ __align__(16) float g_h1[2][BATCH * HID];
__device__ __align__(16) float g_h2[2][BATCH * HID];
__device__ __align__(16) float g_c1[2][BATCH * HID];
__device__ __align__(16) float g_c2[2][BATCH * HID];
__device__ __align__(16) float g_lossbuf[T_STEPS * BATCH];
__device__ unsigned g_tilecnt[2][NT];     // zero-init; reset after each use
__device__ volatile unsigned g_bar_gen;
__device__ unsigned g_bar_cnt;

__device__ __forceinline__ float sigm(float x) {
    return 1.0f / (1.0f + __expf(-x));
}

// packed fp32x2 helpers (FFMA2 path — ptxas never emits it from C++)
__device__ __forceinline__ void ffma2(unsigned long long& d,
                                      unsigned long long a,
                                      unsigned long long b) {
    asm("fma.rn.f32x2 %0, %1, %2, %0;" : "+l"(d) : "l"(a), "l"(b));
}
__device__ __forceinline__ unsigned long long pack2(float x) {
    unsigned long long r;
    asm("mov.b64 %0, {%1, %1};" : "=l"(r) : "f"(x));
    return r;
}
__device__ __forceinline__ float2 unpack2(unsigned long long v) {
    float2 r;
    asm("mov.b64 {%0, %1}, %2;" : "=f"(r.x), "=f"(r.y) : "l"(v));
    return r;
}

// ---------------- grid-wide barrier (all NBLK blocks resident) ----------------
__device__ __forceinline__ void grid_barrier() {
    __syncthreads();
    __threadfence();
    if (threadIdx.x == 0) {
        unsigned gen = g_bar_gen;
        if (atomicAdd(&g_bar_cnt, 1u) == NBLK - 1) {
            g_bar_cnt = 0;
            __threadfence();
            g_bar_gen = gen + 1;
        } else {
            while (g_bar_gen == gen) { __nanosleep(64); }
        }
    }
    __syncthreads();
}

// ---------------- fused GEMM + gate phase for one layer ------------------------
// LAYER 1: A = [x_t (128) | h1[rp] (1024)], Ktot=1152
// LAYER 2: A = [h1[wp] (1024) | h2[rp] (1024)], Ktot=2048
// tile columns: c in [0,128) -> z col (c/32)*HID + tile*32 + c%32
// Last-arriving split-K block applies gates for this tile's 32 hidden units.
template <int LAYER>
__device__ void gemm_gate_phase(
    const float* __restrict__ x0, const float* __restrict__ W,
    const float* __restrict__ bias,
    int t, int rp, int ks, int tile,
    float (*As)[128], float (*Bs)[128])
{
    constexpr int KTOT = (LAYER == 1) ? (DIM + HID) : (2 * HID);
    constexpr int XD   = (LAYER == 1) ? DIM : HID;
    constexpr int KC   = KTOT / KS;
    constexpr int LDA0 = (LAYER == 1) ? DIM : HID;
    constexpr int NTILE = KC / 16;

    int wp = rp ^ 1;
    const float* A0 = (LAYER == 1) ? (x0 + (size_t)t * BATCH * DIM) : g_h1[wp];
    const float* A1 = (LAYER == 1) ? g_h1[rp] : g_h2[rp];
    const float* cprev = (LAYER == 1) ? g_c1[rp] : g_c2[rp];
    float* cnew = (LAYER == 1) ? g_c1[wp] : g_c2[wp];
    float* hnew = (LAYER == 1) ? g_h1[wp] : g_h2[wp];

    int nb = tile * NH;
    int tid = threadIdx.x;
    int tx = tid & 15, ty = tid >> 4;
    int kbase = ks * KC;

    // precomputed per-thread load coordinates
    int m0 = tid >> 2,          kq0 = (tid & 3) * 4;
    int m1 = (tid + 256) >> 2,  kq1 = ((tid + 256) & 3) * 4;
    int kk0 = tid >> 5,         c40 = (tid & 31) * 4;
    int kk1 = (tid + 256) >> 5, c41 = ((tid + 256) & 31) * 4;
    int col0 = (c40 >> 5) * HID + nb + (c40 & 31);
    int col1 = (c41 >> 5) * HID + nb + (c41 & 31);

    unsigned long long acc2[8][4];
#pragma unroll
    for (int i = 0; i < 8; i++)
#pragma unroll
        for (int j = 0; j < 4; j++) acc2[i][j] = 0ull;

    float4 ra0, ra1, rb0, rb1;

    // prologue: load tile 0
    {
        int kg = kbase;
        const float* Asrc = (kg < XD) ? A0 : A1;
        int koff = (kg < XD) ? kg : (kg - XD);
        int lda  = (kg < XD) ? LDA0 : HID;
        ra0 = *(const float4*)(Asrc + (size_t)m0 * lda + koff + kq0);
        ra1 = *(const float4*)(Asrc + (size_t)m1 * lda + koff + kq1);
        rb0 = *(const float4*)(W + (size_t)(kg + kk0) * G4 + col0);
        rb1 = *(const float4*)(W + (size_t)(kg + kk1) * G4 + col1);
    }

    for (int it = 0; it < NTILE; it++) {
        __syncthreads();   // prior compute done; smem free
        As[kq0 + 0][m0] = ra0.x; As[kq0 + 1][m0] = ra0.y;
        As[kq0 + 2][m0] = ra0.z; As[kq0 + 3][m0] = ra0.w;
        As[kq1 + 0][m1] = ra1.x; As[kq1 + 1][m1] = ra1.y;
        As[kq1 + 2][m1] = ra1.z; As[kq1 + 3][m1] = ra1.w;
        *(float4*)&Bs[kk0][c40] = rb0;
        *(float4*)&Bs[kk1][c41] = rb1;
        __syncthreads();

        if (it + 1 < NTILE) {   // prefetch next tile (hidden under compute)
            int kg = kbase + (it + 1) * 16;
            const float* Asrc = (kg < XD) ? A0 : A1;
            int koff = (kg < XD) ? kg : (kg - XD);
            int lda  = (kg < XD) ? LDA0 : HID;
            ra0 = *(const float4*)(Asrc + (size_t)m0 * lda + koff + kq0);
            ra1 = *(const float4*)(Asrc + (size_t)m1 * lda + koff + kq1);
            rb0 = *(const float4*)(W + (size_t)(kg + kk0) * G4 + col0);
            rb1 = *(const float4*)(W + (size_t)(kg + kk1) * G4 + col1);
        }

#pragma unroll
        for (int k = 0; k < 16; k++) {
            float4 a0 = *(const float4*)&As[k][ty * 4];
            float4 a1 = *(const float4*)&As[k][ty * 4 + 64];
            ulonglong2 bb0 = *(const ulonglong2*)&Bs[k][tx * 4];
            ulonglong2 bb1 = *(const ulonglong2*)&Bs[k][tx * 4 + 64];
            unsigned long long b2[4] = {bb0.x, bb0.y, bb1.x, bb1.y};
            float av[8] = {a0.x, a0.y, a0.z, a0.w, a1.x, a1.y, a1.z, a1.w};
#pragma unroll
            for (int i = 0; i < 8; i++) {
                unsigned long long a2 = pack2(av[i]);
#pragma unroll
                for (int j = 0; j < 4; j++)
                    ffma2(acc2[i][j], a2, b2[j]);
            }
        }
    }

    // write split-K partial
    float* zp = g_zpart + ((size_t)ks * NT + tile) * (BATCH * 128);
#pragma unroll
    for (int i = 0; i < 8; i++) {
        int m = (i < 4) ? (ty * 4 + i) : (64 + ty * 4 + i - 4);
        float* zr = zp + (size_t)m * 128;
        *(float2*)(zr + tx * 4)      = unpack2(acc2[i][0]);
        *(float2*)(zr + tx * 4 + 2)  = unpack2(acc2[i][1]);
        *(float2*)(zr + tx * 4 + 64) = unpack2(acc2[i][2]);
        *(float2*)(zr + tx * 4 + 66) = unpack2(acc2[i][3]);
    }

    // per-tile split-K rendezvous: last-arriving block applies gates
    __shared__ int s_last;
    __threadfence();                 // publish this thread's partial stores
    __syncthreads();
    if (tid == 0)
        s_last = (atomicAdd(&g_tilecnt[LAYER - 1][tile], 1u) == KS - 1) ? 1 : 0;
    __syncthreads();
    if (!s_last) return;
    __threadfence();                 // acquire: invalidate stale L1, see peers' partials
    if (tid == 0) g_tilecnt[LAYER - 1][tile] = 0;   // reset (guarded by grid barrier)

    // gates: this tile's 32 hidden units x 128 batch = 4096 elems, 16/thread
#pragma unroll
    for (int e = 0; e < 16; e++) {
        int idx = e * 256 + tid;
        int b  = idx >> 5;
        int hh = idx & 31;
        float zi = 0.f, zj = 0.f, zf = 0.f, zo = 0.f;
#pragma unroll
        for (int s = 0; s < KS; s++) {
            const float* z = g_zpart + ((size_t)s * NT + tile) * (BATCH * 128)
                           + (size_t)b * 128;
            zi += z[hh]; zj += z[32 + hh]; zf += z[64 + hh]; zo += z[96 + hh];
        }
        int hg = nb + hh;
        zi += bias[hg];
        zj += bias[HID + hg];
        zf += bias[2 * HID + hg];
        zo += bias[3 * HID + hg];

        int bidx = b * HID + hg;
        float cp = cprev[bidx];
        float fg = sigm(zf + 1.0f);
        float ig = sigm(zi);
        float jg = tanhf(zj);
        float og = sigm(zo);
        float cn = cp * fg + ig * jg;
        float hn = tanhf(cn) * og;
        cnew[bidx] = cn;
        hnew[bidx] = hn;
        if (LAYER == 2)
            g_h2all[(size_t)t * BATCH * HID + bidx] = hn;
    }
}

// ---------------- persistent recurrence kernel ---------------------------------
__global__ __launch_bounds__(NTHR, 1) void lstm_persistent_kernel(
    const float* __restrict__ inSeq,
    const float* __restrict__ W1, const float* __restrict__ b1,
    const float* __restrict__ W2, const float* __restrict__ b2)
{
    __shared__ __align__(16) float As[16][128];
    __shared__ __align__(16) float Bs[16][128];

    int bid = blockIdx.x;
    int tile = bid & 31, ks = bid >> 5;
    int gid = bid * NTHR + threadIdx.x;

    for (int i = gid; i < BATCH * HID; i += NBLK * NTHR) {
        g_h1[0][i] = 0.f; g_h2[0][i] = 0.f;
        g_c1[0][i] = 0.f; g_c2[0][i] = 0.f;
    }
    grid_barrier();

    for (int t = 0; t < T_STEPS; t++) {
        int rp = t & 1;
        gemm_gate_phase<1>(inSeq, W1, b1, t, rp, ks, tile, As, Bs);
        grid_barrier();
        gemm_gate_phase<2>(nullptr, W2, b2, t, rp, ks, tile, As, Bs);
        grid_barrier();
    }
}

// ---------------- logits = g_h2all @ outW + outB ------------------------------
__global__ __launch_bounds__(256) void logits_kernel(
    const float* __restrict__ W, const float* __restrict__ bias)
{
    int mt = blockIdx.x;
    __shared__ __align__(16) float As[16][128];
    __shared__ __align__(16) float Bs[16][128];
    int tid = threadIdx.x;
    int tx = tid & 15, ty = tid >> 4;
    float acc[8][8];
#pragma unroll
    for (int i = 0; i < 8; i++)
#pragma unroll
        for (int j = 0; j < 8; j++) acc[i][j] = 0.f;

    const float* Ab = g_h2all + (size_t)mt * 128 * HID;

    for (int k0 = 0; k0 < HID; k0 += 16) {
#pragma unroll
        for (int r = 0; r < 2; r++) {
            int p = tid + r * 256;
            int m = p >> 2, kq = (p & 3) * 4;
            float4 v = *(const float4*)(Ab + (size_t)m * HID + k0 + kq);
            As[kq + 0][m] = v.x; As[kq + 1][m] = v.y;
            As[kq + 2][m] = v.z; As[kq + 3][m] = v.w;
        }
#pragma unroll
        for (int r = 0; r < 2; r++) {
            int p = tid + r * 256;
            int kk = p >> 5, c4 = (p & 31) * 4;
            float4 v = *(const float4*)(W + (size_t)(k0 + kk) * DIM + c4);
            *(float4*)&Bs[kk][c4] = v;
        }
        __syncthreads();
#pragma unroll
        for (int k = 0; k < 16; k++) {
            float4 a0 = *(const float4*)&As[k][ty * 4];
            float4 a1 = *(const float4*)&As[k][ty * 4 + 64];
            float4 b0 = *(const float4*)&Bs[k][tx * 4];
            float4 b1 = *(const float4*)&Bs[k][tx * 4 + 64];
            float av[8] = {a0.x, a0.y, a0.z, a0.w, a1.x, a1.y, a1.z, a1.w};
            float bv[8] = {b0.x, b0.y, b0.z, b0.w, b1.x, b1.y, b1.z, b1.w};
#pragma unroll
            for (int i = 0; i < 8; i++)
#pragma unroll
                for (int j = 0; j < 8; j++)
                    acc[i][j] = fmaf(av[i], bv[j], acc[i][j]);
        }
        __syncthreads();
    }

#pragma unroll
    for (int i = 0; i < 8; i++) {
        int m = (i < 4) ? (ty * 4 + i) : (64 + ty * 4 + i - 4);
        float* orow = g_logits + (size_t)(mt * 128 + m) * DIM;
        int c0 = tx * 4;
        float4 o0, o1;
        o0.x = acc[i][0] + bias[c0 + 0];
        o0.y = acc[i][1] + bias[c0 + 1];
        o0.z = acc[i][2] + bias[c0 + 2];
        o0.w = acc[i][3] + bias[c0 + 3];
        o1.x = acc[i][4] + bias[c0 + 64];
        o1.y = acc[i][5] + bias[c0 + 65];
        o1.z = acc[i][6] + bias[c0 + 66];
        o1.w = acc[i][7] + bias[c0 + 67];
        *(float4*)(orow + c0) = o0;
        *(float4*)(orow + c0 + 64) = o1;
    }
}

// ---------------- dual softmax + probs + CE (warp per row) ---------------------
__global__ __launch_bounds__(256) void softmax_ce_kernel(
    const int* __restrict__ tgt, float* __restrict__ probs)
{
    int warp = (blockIdx.x * blockDim.x + threadIdx.x) >> 5;
    int lane = threadIdx.x & 31;
    if (warp >= T_STEPS * BATCH) return;
    const float* row = g_logits + (size_t)warp * 128;
    float v0 = row[lane], v1 = row[lane + 32], v2 = row[lane + 64], v3 = row[lane + 96];

    float m_mel = fmaxf(v0, lane < 16 ? v1 : -1e30f);
#pragma unroll
    for (int o = 16; o; o >>= 1) m_mel = fmaxf(m_mel, __shfl_xor_sync(~0u, m_mel, o));
    float e0 = __expf(v0 - m_mel);
    float e1m = (lane < 16) ? __expf(v1 - m_mel) : 0.f;
    float s_mel = e0 + e1m;
#pragma unroll
    for (int o = 16; o; o >>= 1) s_mel += __shfl_xor_sync(~0u, s_mel, o);

    float m_har = fmaxf(fmaxf(v2, v3), lane >= 16 ? v1 : -1e30f);
#pragma unroll
    for (int o = 16; o; o >>= 1) m_har = fmaxf(m_har, __shfl_xor_sync(~0u, m_har, o));
    float e1h = (lane >= 16) ? __expf(v1 - m_har) : 0.f;
    float e2 = __expf(v2 - m_har);
    float e3 = __expf(v3 - m_har);
    float s_har = e1h + e2 + e3;
#pragma unroll
    for (int o = 16; o; o >>= 1) s_har += __shfl_xor_sync(~0u, s_har, o);

    float inv_mel = 1.0f / s_mel;
    float inv_har = 1.0f / s_har;
    float* pr = probs + (size_t)warp * 128;
    pr[lane]      = e0 * inv_mel;
    pr[lane + 32] = (lane < 16) ? e1m * inv_mel : e1h * inv_har;
    pr[lane + 64] = e2 * inv_har;
    pr[lane + 96] = e3 * inv_har;

    if (lane == 0) {
        int t0 = tgt[warp * 2 + 0];
        int t1 = tgt[warp * 2 + 1];
        t0 = min(max(t0, 0), 47);
        t1 = min(max(t1, 0), 79);
        float l0 = row[t0];
        float l1 = row[48 + t1];
        float lse_mel = m_mel + logf(s_mel);
        float lse_har = m_har + logf(s_har);
        g_lossbuf[warp] = 0.5f * (lse_mel - l0) + 0.5f * (lse_har - l1);
    }
}

__global__ __launch_bounds__(256) void loss_reduce_kernel(float* __restrict__ out)
{
    __shared__ float sm[256];
    float s = 0.f;
    for (int i = threadIdx.x; i < T_STEPS * BATCH; i += 256) s += g_lossbuf[i];
    sm[threadIdx.x] = s;
    __syncthreads();
    for (int o = 128; o; o >>= 1) {
        if (threadIdx.x < o) sm[threadIdx.x] += sm[threadIdx.x + o];
        __syncthreads();
    }
    if (threadIdx.x == 0)
        out[0] = sm[0] / (float)(T_STEPS * BATCH);
}

// ---------------- launch (4 graph nodes) ---------------------------------------
extern "C" void kernel_launch(void* const* d_in, const int* in_sizes, int n_in,
                              void* d_out, int out_size)
{
    const float* inSeq = (const float*)d_in[0];
    const int*   tgt   = (const int*)d_in[1];     // int32 targets
    const float* W1    = (const float*)d_in[2];
    const float* b1    = (const float*)d_in[3];
    const float* W2    = (const float*)d_in[4];
    const float* b2    = (const float*)d_in[5];
    const float* outW  = (const float*)d_in[6];
    const float* outB  = (const float*)d_in[7];
    float* out = (float*)d_out;

    lstm_persistent_kernel<<<NBLK, NTHR>>>(inSeq, W1, b1, W2, b2);

    logits_kernel<<<(T_STEPS * BATCH) / 128, 256>>>(outW, outB);

    softmax_ce_kernel<<<(T_STEPS * BATCH * 32) / 256, 256>>>(tgt, out);

    loss_reduce_kernel<<<1, 256>>>(out + (out_size - 1));
}

// round 8
// speedup vs baseline: 1.1536x; 1.1536x over previous
#include <cuda_runtime.h>
#include <math.h>
#include <stdint.h>

#define T_STEPS 256
#define BATCH   128
#define DIM     128
#define HID     1024
#define G4      4096      // 4*HID
#define NT      32        // hidden tiles per layer (HID/NH)
#define NH      32        // hidden units per tile -> 128 z columns
#define KS      4         // split-K factor
#define NBLK    128       // persistent blocks = KS*NT (all resident on 148 SMs)
#define NTHR    256

// ---------------- device scratch ----------------------------------------------
__device__ __align__(16) float g_h2all[(size_t)T_STEPS * BATCH * HID];
__device__ __align__(16) float g_logits[(size_t)T_STEPS * BATCH * DIM];
__device__ __align__(16) float g_zpart[(size_t)KS * NT * BATCH * 128];
__device__ __align__(16) float g_h1[BATCH * HID];
__device__ __align__(16) float g_h2[BATCH * HID];
__device__ __align__(16) float g_c1[BATCH * HID];
__device__ __align__(16) float g_c2[BATCH * HID];
__device__ __align__(16) float g_lossbuf[T_STEPS * BATCH];
__device__ volatile unsigned g_bar_gen;   // zero-initialized at module load
__device__ unsigned g_bar_cnt;

__device__ __forceinline__ float sigm(float x) {
    return 1.0f / (1.0f + __expf(-x));
}

// packed fp32x2 helpers (FFMA2 path — ptxas never emits it from C++)
__device__ __forceinline__ void ffma2(unsigned long long& d,
                                      unsigned long long a,
                                      unsigned long long b) {
    asm("fma.rn.f32x2 %0, %1, %2, %0;" : "+l"(d) : "l"(a), "l"(b));
}
__device__ __forceinline__ unsigned long long pack2(float x) {
    unsigned long long r;
    asm("mov.b64 %0, {%1, %1};" : "=l"(r) : "f"(x));
    return r;
}
__device__ __forceinline__ float2 unpack2(unsigned long long v) {
    float2 r;
    asm("mov.b64 {%0, %1}, %2;" : "=f"(r.x), "=f"(r.y) : "l"(v));
    return r;
}

// ---------------- grid-wide barrier (all NBLK blocks resident) ----------------
__device__ __forceinline__ void grid_barrier() {
    __syncthreads();
    __threadfence();
    if (threadIdx.x == 0) {
        unsigned gen = g_bar_gen;            // read BEFORE arriving
        if (atomicAdd(&g_bar_cnt, 1u) == NBLK - 1) {
            g_bar_cnt = 0;
            __threadfence();
            g_bar_gen = gen + 1;             // release
        } else {
            while (g_bar_gen == gen) { __nanosleep(64); }
        }
    }
    __syncthreads();
}

// ---------------- GEMM phase for one layer (writes split-K partials) ----------
// LAYER 1: A = [x_t (128) | h1 (1024)], Ktot=1152 ; LAYER 2: A = [h1 | h2], 2048
// tile columns: c in [0,128) -> global z col (c/32)*HID + tile*32 + c%32
template <int LAYER>
__device__ void gemm_phase(const float* __restrict__ x0, const float* __restrict__ W,
                           int t, int ks, int tile,
                           float (*As)[128], float (*Bs)[128])
{
    constexpr int KTOT = (LAYER == 1) ? (DIM + HID) : (2 * HID);
    constexpr int XD   = (LAYER == 1) ? DIM : HID;
    constexpr int KC   = KTOT / KS;
    constexpr int LDA0 = (LAYER == 1) ? DIM : HID;
    constexpr int NTILE = KC / 16;

    const float* A0 = (LAYER == 1) ? (x0 + (size_t)t * BATCH * DIM) : g_h1;
    const float* A1 = (LAYER == 1) ? g_h1 : g_h2;

    int nb = tile * NH;
    int tid = threadIdx.x;
    int tx = tid & 15, ty = tid >> 4;
    int kbase = ks * KC;

    // per-thread load coordinates (fixed across tiles)
    int m0 = tid >> 2,          kq0 = (tid & 3) * 4;
    int m1 = (tid + 256) >> 2,  kq1 = ((tid + 256) & 3) * 4;
    int kk0 = tid >> 5,         c40 = (tid & 31) * 4;
    int kk1 = (tid + 256) >> 5, c41 = ((tid + 256) & 31) * 4;
    int col0 = (c40 >> 5) * HID + nb + (c40 & 31);
    int col1 = (c41 >> 5) * HID + nb + (c41 & 31);

    unsigned long long acc2[8][4];
#pragma unroll
    for (int i = 0; i < 8; i++)
#pragma unroll
        for (int j = 0; j < 4; j++) acc2[i][j] = 0ull;

    float4 ra0, ra1, rb0, rb1;

    // prologue: load k-tile 0 into registers
    {
        int kg = kbase;
        const float* Asrc = (kg < XD) ? A0 : A1;
        int koff = (kg < XD) ? kg : (kg - XD);
        int lda  = (kg < XD) ? LDA0 : HID;
        ra0 = *(const float4*)(Asrc + (size_t)m0 * lda + koff + kq0);
        ra1 = *(const float4*)(Asrc + (size_t)m1 * lda + koff + kq1);
        rb0 = *(const float4*)(W + (size_t)(kg + kk0) * G4 + col0);
        rb1 = *(const float4*)(W + (size_t)(kg + kk1) * G4 + col1);
    }

    for (int it = 0; it < NTILE; it++) {
        __syncthreads();   // prior tile's compute done; smem reusable
        As[kq0 + 0][m0] = ra0.x; As[kq0 + 1][m0] = ra0.y;
        As[kq0 + 2][m0] = ra0.z; As[kq0 + 3][m0] = ra0.w;
        As[kq1 + 0][m1] = ra1.x; As[kq1 + 1][m1] = ra1.y;
        As[kq1 + 2][m1] = ra1.z; As[kq1 + 3][m1] = ra1.w;
        *(float4*)&Bs[kk0][c40] = rb0;
        *(float4*)&Bs[kk1][c41] = rb1;
        __syncthreads();

        if (it + 1 < NTILE) {   // prefetch next k-tile; hidden under compute
            int kg = kbase + (it + 1) * 16;
            const float* Asrc = (kg < XD) ? A0 : A1;
            int koff = (kg < XD) ? kg : (kg - XD);
            int lda  = (kg < XD) ? LDA0 : HID;
            ra0 = *(const float4*)(Asrc + (size_t)m0 * lda + koff + kq0);
            ra1 = *(const float4*)(Asrc + (size_t)m1 * lda + koff + kq1);
            rb0 = *(const float4*)(W + (size_t)(kg + kk0) * G4 + col0);
            rb1 = *(const float4*)(W + (size_t)(kg + kk1) * G4 + col1);
        }

#pragma unroll
        for (int k = 0; k < 16; k++) {
            float4 a0 = *(const float4*)&As[k][ty * 4];
            float4 a1 = *(const float4*)&As[k][ty * 4 + 64];
            ulonglong2 bb0 = *(const ulonglong2*)&Bs[k][tx * 4];
            ulonglong2 bb1 = *(const ulonglong2*)&Bs[k][tx * 4 + 64];
            unsigned long long b2[4] = {bb0.x, bb0.y, bb1.x, bb1.y};
            float av[8] = {a0.x, a0.y, a0.z, a0.w, a1.x, a1.y, a1.z, a1.w};
#pragma unroll
            for (int i = 0; i < 8; i++) {
                unsigned long long a2 = pack2(av[i]);
#pragma unroll
                for (int j = 0; j < 4; j++)
                    ffma2(acc2[i][j], a2, b2[j]);
            }
        }
    }

    float* zp = g_zpart + ((size_t)ks * NT + tile) * (BATCH * 128);
#pragma unroll
    for (int i = 0; i < 8; i++) {
        int m = (i < 4) ? (ty * 4 + i) : (64 + ty * 4 + i - 4);
        float* zr = zp + (size_t)m * 128;
        *(float2*)(zr + tx * 4)      = unpack2(acc2[i][0]);
        *(float2*)(zr + tx * 4 + 2)  = unpack2(acc2[i][1]);
        *(float2*)(zr + tx * 4 + 64) = unpack2(acc2[i][2]);
        *(float2*)(zr + tx * 4 + 66) = unpack2(acc2[i][3]);
    }
}

// ---------------- gate phase: reduce split-K partials + LSTM nonlinearity -----
template <int LAYER>
__device__ void gate_phase(const float* __restrict__ bias, int t, int gid)
{
    const float* cbuf = (LAYER == 1) ? g_c1 : g_c2;
    float* cw = (LAYER == 1) ? g_c1 : g_c2;
    float* hw = (LAYER == 1) ? g_h1 : g_h2;

#pragma unroll
    for (int e = 0; e < (BATCH * HID) / (NBLK * NTHR); e++) {
        int idx = gid + e * (NBLK * NTHR);
        int b  = idx >> 10;
        int hg = idx & (HID - 1);
        int tile = hg >> 5;
        int hh = hg & 31;

        float zi = 0.f, zj = 0.f, zf = 0.f, zo = 0.f;
#pragma unroll
        for (int s = 0; s < KS; s++) {
            const float* z = g_zpart + ((size_t)s * NT + tile) * (BATCH * 128)
                           + (size_t)b * 128;
            zi += z[hh]; zj += z[32 + hh]; zf += z[64 + hh]; zo += z[96 + hh];
        }
        zi += bias[hg];
        zj += bias[HID + hg];
        zf += bias[2 * HID + hg];
        zo += bias[3 * HID + hg];

        float cp = cbuf[idx];
        float fg = sigm(zf + 1.0f);
        float ig = sigm(zi);
        float jg = tanhf(zj);
        float og = sigm(zo);
        float cn = cp * fg + ig * jg;
        float hn = tanhf(cn) * og;
        cw[idx] = cn;
        hw[idx] = hn;
        if (LAYER == 2)
            g_h2all[(size_t)t * BATCH * HID + idx] = hn;
    }
}

// ---------------- persistent recurrence kernel: all 256 steps, 1 launch -------
__global__ __launch_bounds__(NTHR, 1) void lstm_persistent_kernel(
    const float* __restrict__ inSeq,
    const float* __restrict__ W1, const float* __restrict__ b1,
    const float* __restrict__ W2, const float* __restrict__ b2)
{
    __shared__ __align__(16) float As[16][128];
    __shared__ __align__(16) float Bs[16][128];

    int bid = blockIdx.x;
    int tile = bid & 31, ks = bid >> 5;
    int gid = bid * NTHR + threadIdx.x;

    for (int i = gid; i < BATCH * HID; i += NBLK * NTHR) {
        g_h1[i] = 0.f; g_h2[i] = 0.f; g_c1[i] = 0.f; g_c2[i] = 0.f;
    }
    grid_barrier();

    for (int t = 0; t < T_STEPS; t++) {
        gemm_phase<1>(inSeq, W1, t, ks, tile, As, Bs);
        grid_barrier();
        gate_phase<1>(b1, t, gid);
        grid_barrier();
        gemm_phase<2>(nullptr, W2, t, ks, tile, As, Bs);
        grid_barrier();
        gate_phase<2>(b2, t, gid);
        grid_barrier();
    }
}

// ---------------- logits = g_h2all @ outW + outB ------------------------------
__global__ __launch_bounds__(256) void logits_kernel(
    const float* __restrict__ W, const float* __restrict__ bias)
{
    int mt = blockIdx.x;
    __shared__ __align__(16) float As[16][128];
    __shared__ __align__(16) float Bs[16][128];
    int tid = threadIdx.x;
    int tx = tid & 15, ty = tid >> 4;
    float acc[8][8];
#pragma unroll
    for (int i = 0; i < 8; i++)
#pragma unroll
        for (int j = 0; j < 8; j++) acc[i][j] = 0.f;

    const float* Ab = g_h2all + (size_t)mt * 128 * HID;

    for (int k0 = 0; k0 < HID; k0 += 16) {
#pragma unroll
        for (int r = 0; r < 2; r++) {
            int p = tid + r * 256;
            int m = p >> 2, kq = (p & 3) * 4;
            float4 v = *(const float4*)(Ab + (size_t)m * HID + k0 + kq);
            As[kq + 0][m] = v.x; As[kq + 1][m] = v.y;
            As[kq + 2][m] = v.z; As[kq + 3][m] = v.w;
        }
#pragma unroll
        for (int r = 0; r < 2; r++) {
            int p = tid + r * 256;
            int kk = p >> 5, c4 = (p & 31) * 4;
            float4 v = *(const float4*)(W + (size_t)(k0 + kk) * DIM + c4);
            *(float4*)&Bs[kk][c4] = v;
        }
        __syncthreads();
#pragma unroll
        for (int k = 0; k < 16; k++) {
            float4 a0 = *(const float4*)&As[k][ty * 4];
            float4 a1 = *(const float4*)&As[k][ty * 4 + 64];
            float4 b0 = *(const float4*)&Bs[k][tx * 4];
            float4 b1 = *(const float4*)&Bs[k][tx * 4 + 64];
            float av[8] = {a0.x, a0.y, a0.z, a0.w, a1.x, a1.y, a1.z, a1.w};
            float bv[8] = {b0.x, b0.y, b0.z, b0.w, b1.x, b1.y, b1.z, b1.w};
#pragma unroll
            for (int i = 0; i < 8; i++)
#pragma unroll
                for (int j = 0; j < 8; j++)
                    acc[i][j] = fmaf(av[i], bv[j], acc[i][j]);
        }
        __syncthreads();
    }

#pragma unroll
    for (int i = 0; i < 8; i++) {
        int m = (i < 4) ? (ty * 4 + i) : (64 + ty * 4 + i - 4);
        float* orow = g_logits + (size_t)(mt * 128 + m) * DIM;
        int c0 = tx * 4;
        float4 o0, o1;
        o0.x = acc[i][0] + bias[c0 + 0];
        o0.y = acc[i][1] + bias[c0 + 1];
        o0.z = acc[i][2] + bias[c0 + 2];
        o0.w = acc[i][3] + bias[c0 + 3];
        o1.x = acc[i][4] + bias[c0 + 64];
        o1.y = acc[i][5] + bias[c0 + 65];
        o1.z = acc[i][6] + bias[c0 + 66];
        o1.w = acc[i][7] + bias[c0 + 67];
        *(float4*)(orow + c0) = o0;
        *(float4*)(orow + c0 + 64) = o1;
    }
}

// ---------------- dual softmax + probs + CE (warp per row) ---------------------
__global__ __launch_bounds__(256) void softmax_ce_kernel(
    const int* __restrict__ tgt, float* __restrict__ probs)
{
    int warp = (blockIdx.x * blockDim.x + threadIdx.x) >> 5;
    int lane = threadIdx.x & 31;
    if (warp >= T_STEPS * BATCH) return;
    const float* row = g_logits + (size_t)warp * 128;
    float v0 = row[lane], v1 = row[lane + 32], v2 = row[lane + 64], v3 = row[lane + 96];

    float m_mel = fmaxf(v0, lane < 16 ? v1 : -1e30f);
#pragma unroll
    for (int o = 16; o; o >>= 1) m_mel = fmaxf(m_mel, __shfl_xor_sync(~0u, m_mel, o));
    float e0 = __expf(v0 - m_mel);
    float e1m = (lane < 16) ? __expf(v1 - m_mel) : 0.f;
    float s_mel = e0 + e1m;
#pragma unroll
    for (int o = 16; o; o >>= 1) s_mel += __shfl_xor_sync(~0u, s_mel, o);

    float m_har = fmaxf(fmaxf(v2, v3), lane >= 16 ? v1 : -1e30f);
#pragma unroll
    for (int o = 16; o; o >>= 1) m_har = fmaxf(m_har, __shfl_xor_sync(~0u, m_har, o));
    float e1h = (lane >= 16) ? __expf(v1 - m_har) : 0.f;
    float e2 = __expf(v2 - m_har);
    float e3 = __expf(v3 - m_har);
    float s_har = e1h + e2 + e3;
#pragma unroll
    for (int o = 16; o; o >>= 1) s_har += __shfl_xor_sync(~0u, s_har, o);

    float inv_mel = 1.0f / s_mel;
    float inv_har = 1.0f / s_har;
    float* pr = probs + (size_t)warp * 128;
    pr[lane]      = e0 * inv_mel;
    pr[lane + 32] = (lane < 16) ? e1m * inv_mel : e1h * inv_har;
    pr[lane + 64] = e2 * inv_har;
    pr[lane + 96] = e3 * inv_har;

    if (lane == 0) {
        int t0 = tgt[warp * 2 + 0];
        int t1 = tgt[warp * 2 + 1];
        t0 = min(max(t0, 0), 47);
        t1 = min(max(t1, 0), 79);
        float l0 = row[t0];
        float l1 = row[48 + t1];
        float lse_mel = m_mel + logf(s_mel);
        float lse_har = m_har + logf(s_har);
        g_lossbuf[warp] = 0.5f * (lse_mel - l0) + 0.5f * (lse_har - l1);
    }
}

__global__ __launch_bounds__(256) void loss_reduce_kernel(float* __restrict__ out)
{
    __shared__ float sm[256];
    float s = 0.f;
    for (int i = threadIdx.x; i < T_STEPS * BATCH; i += 256) s += g_lossbuf[i];
    sm[threadIdx.x] = s;
    __syncthreads();
    for (int o = 128; o; o >>= 1) {
        if (threadIdx.x < o) sm[threadIdx.x] += sm[threadIdx.x + o];
        __syncthreads();
    }
    if (threadIdx.x == 0)
        out[0] = sm[0] / (float)(T_STEPS * BATCH);
}

// ---------------- launch (4 graph nodes) ---------------------------------------
extern "C" void kernel_launch(void* const* d_in, const int* in_sizes, int n_in,
                              void* d_out, int out_size)
{
    const float* inSeq = (const float*)d_in[0];
    const int*   tgt   = (const int*)d_in[1];     // int32 targets
    const float* W1    = (const float*)d_in[2];
    const float* b1    = (const float*)d_in[3];
    const float* W2    = (const float*)d_in[4];
    const float* b2    = (const float*)d_in[5];
    const float* outW  = (const float*)d_in[6];
    const float* outB  = (const float*)d_in[7];
    float* out = (float*)d_out;

    lstm_persistent_kernel<<<NBLK, NTHR>>>(inSeq, W1, b1, W2, b2);

    logits_kernel<<<(T_STEPS * BATCH) / 128, 256>>>(outW, outB);

    softmax_ce_kernel<<<(T_STEPS * BATCH * 32) / 256, 256>>>(tgt, out);

    loss_reduce_kernel<<<1, 256>>>(out + (out_size - 1));
}

// round 10
// speedup vs baseline: 1.8665x; 1.6181x over previous
#include <cuda_runtime.h>
#include <cuda_bf16.h>
#include <math.h>
#include <stdint.h>

#define T_STEPS 256
#define BATCH   128
#define DIM     128
#define HID     1024
#define G4      4096
#define NT      32        // weight tiles per layer (128 z-cols each)
#define KS      4         // split-K
#define NBLK    128
#define NTHR    256
#define KT1     1152      // DIM + HID
#define KT2     2048      // 2*HID
#define KC      32        // k per smem chunk
#define SP      40        // smem row stride (bf16) — conflict-free

// ---------------- fp32 scratch -------------------------------------------------
__device__ __align__(16) float g_h2all[(size_t)T_STEPS * BATCH * HID];
__device__ __align__(16) float g_logits[(size_t)T_STEPS * BATCH * DIM];
__device__ __align__(16) float g_zpart[(size_t)KS * NT * BATCH * 128];
__device__ __align__(16) float g_c1[BATCH * HID];
__device__ __align__(16) float g_c2[BATCH * HID];
__device__ __align__(16) float g_lossbuf[T_STEPS * BATCH];
__device__ volatile unsigned g_bar_gen;
__device__ unsigned g_bar_cnt;

// ---------------- bf16 split operands ------------------------------------------
__device__ __align__(16) __nv_bfloat16 g_x_hi[(size_t)T_STEPS * BATCH * DIM];
__device__ __align__(16) __nv_bfloat16 g_x_lo[(size_t)T_STEPS * BATCH * DIM];
__device__ __align__(16) __nv_bfloat16 g_w1_hi[(size_t)G4 * KT1];
__device__ __align__(16) __nv_bfloat16 g_w1_lo[(size_t)G4 * KT1];
__device__ __align__(16) __nv_bfloat16 g_w2_hi[(size_t)G4 * KT2];
__device__ __align__(16) __nv_bfloat16 g_w2_lo[(size_t)G4 * KT2];
__device__ __align__(16) __nv_bfloat16 g_h1_hi[BATCH * HID];
__device__ __align__(16) __nv_bfloat16 g_h1_lo[BATCH * HID];
__device__ __align__(16) __nv_bfloat16 g_h2_hi[BATCH * HID];
__device__ __align__(16) __nv_bfloat16 g_h2_lo[BATCH * HID];

__device__ __forceinline__ float sigm(float x) { return 1.0f / (1.0f + __expf(-x)); }

// ---------------- mma.sync m16n8k16 bf16 (portable ISA, runs on HMMA) ----------
__device__ __forceinline__ void mma16816(float* c, const uint32_t* a,
                                         uint32_t b0, uint32_t b1) {
    asm("mma.sync.aligned.m16n8k16.row.col.f32.bf16.bf16.f32 "
        "{%0,%1,%2,%3}, {%4,%5,%6,%7}, {%8,%9}, {%0,%1,%2,%3};"
        : "+f"(c[0]), "+f"(c[1]), "+f"(c[2]), "+f"(c[3])
        : "r"(a[0]), "r"(a[1]), "r"(a[2]), "r"(a[3]), "r"(b0), "r"(b1));
}

// ---------------- grid-wide barrier --------------------------------------------
__device__ __forceinline__ void grid_barrier() {
    __syncthreads();
    __threadfence();
    if (threadIdx.x == 0) {
        unsigned gen = g_bar_gen;
        if (atomicAdd(&g_bar_cnt, 1u) == NBLK - 1) {
            g_bar_cnt = 0;
            __threadfence();
            g_bar_gen = gen + 1;
        } else {
            while (g_bar_gen == gen) { __nanosleep(32); }
        }
    }
    __syncthreads();
}

// ---------------- conversion prolog kernels ------------------------------------
__global__ __launch_bounds__(256) void conv_x_kernel(const float* __restrict__ x) {
    size_t i = (size_t)blockIdx.x * 256 + threadIdx.x;   // over T*B*DIM
    float v = x[i];
    __nv_bfloat16 h = __float2bfloat16(v);
    g_x_hi[i] = h;
    g_x_lo[i] = __float2bfloat16(v - __bfloat162float(h));
}

// W1 [1152][4096] -> per-tile K-major slabs: g_w1[(tile*128 + r)*KT1 + k]
// r in [0,128): gate block (r>>5), unit (r&31); col = (r>>5)*HID + tile*32 + (r&31)
__global__ __launch_bounds__(256) void conv_w1_kernel(const float* __restrict__ W) {
    size_t i = (size_t)blockIdx.x * 256 + threadIdx.x;   // i = k*G4 + np (coalesced read)
    if (i >= (size_t)KT1 * G4) return;
    int np = (int)(i & (G4 - 1));
    int k  = (int)(i >> 12);
    int tile = np >> 7, r = np & 127;
    int col = (r >> 5) * HID + tile * 32 + (r & 31);
    float v = W[(size_t)k * G4 + col];
    __nv_bfloat16 h = __float2bfloat16(v);
    g_w1_hi[(size_t)np * KT1 + k] = h;
    g_w1_lo[(size_t)np * KT1 + k] = __float2bfloat16(v - __bfloat162float(h));
}

__global__ __launch_bounds__(256) void conv_w2_kernel(const float* __restrict__ W) {
    size_t i = (size_t)blockIdx.x * 256 + threadIdx.x;
    if (i >= (size_t)KT2 * G4) return;
    int np = (int)(i & (G4 - 1));
    int k  = (int)(i >> 12);
    int tile = np >> 7, r = np & 127;
    int col = (r >> 5) * HID + tile * 32 + (r & 31);
    float v = W[(size_t)k * G4 + col];
    __nv_bfloat16 h = __float2bfloat16(v);
    g_w2_hi[(size_t)np * KT2 + k] = h;
    g_w2_lo[(size_t)np * KT2 + k] = __float2bfloat16(v - __bfloat162float(h));
}

// ---------------- tile loader: 128 rows x 32 bf16 -> smem [row][SP] ------------
__device__ __forceinline__ void load_tile(__nv_bfloat16* dst,
                                          const __nv_bfloat16* __restrict__ src,
                                          int lda, int koff) {
    int tid = threadIdx.x;
#pragma unroll
    for (int q = 0; q < 2; q++) {
        int i = tid + q * 256;          // [0,512): 16B chunks
        int row = i >> 2, c = i & 3;
        uint4 v = *(const uint4*)(src + (size_t)row * lda + koff + c * 8);
        *(uint4*)(dst + row * SP + c * 8) = v;
    }
}

// ---------------- tensor GEMM phase (one layer slice, mma.sync) ----------------
template <int LAYER>
__device__ void gemm_phase_mma(int t, int ks, int tile,
                               __nv_bfloat16* sAh, __nv_bfloat16* sAl,
                               __nv_bfloat16* sBh, __nv_bfloat16* sBl)
{
    constexpr int KT  = (LAYER == 1) ? KT1 : KT2;
    constexpr int XD  = (LAYER == 1) ? DIM : HID;
    constexpr int KSL = KT / KS;            // 288 / 512
    constexpr int NCH = KSL / KC;           // 9 / 16
    int kbase = ks * KSL;
    int tid = threadIdx.x;
    int w = tid >> 5, lane = tid & 31;
    int mr = (w >> 1) * 32;                 // warp row base (4 rowgroups)
    int nb = (w & 1) * 64;                  // warp col base (2 colgroups)
    int r = lane >> 2, cq = (lane & 3) * 2;

    const __nv_bfloat16* Bh = ((LAYER == 1) ? g_w1_hi : g_w2_hi) + (size_t)tile * 128 * KT;
    const __nv_bfloat16* Bl = ((LAYER == 1) ? g_w1_lo : g_w2_lo) + (size_t)tile * 128 * KT;

    float acc[2][8][4];
#pragma unroll
    for (int a = 0; a < 2; a++)
#pragma unroll
        for (int n = 0; n < 8; n++)
#pragma unroll
            for (int j = 0; j < 4; j++) acc[a][n][j] = 0.f;

    for (int c = 0; c < NCH; c++) {
        int kg = kbase + c * KC;
        const __nv_bfloat16 *Ah, *Al;
        int lda, koff;
        if (LAYER == 1) {
            if (kg < XD) { Ah = g_x_hi + (size_t)t * BATCH * DIM;
                           Al = g_x_lo + (size_t)t * BATCH * DIM; lda = DIM; koff = kg; }
            else         { Ah = g_h1_hi; Al = g_h1_lo; lda = HID; koff = kg - XD; }
        } else {
            if (kg < XD) { Ah = g_h1_hi; Al = g_h1_lo; lda = HID; koff = kg; }
            else         { Ah = g_h2_hi; Al = g_h2_lo; lda = HID; koff = kg - XD; }
        }

        load_tile(sAh, Ah, lda, koff);
        load_tile(sAl, Al, lda, koff);
        load_tile(sBh, Bh, KT, kg);
        load_tile(sBl, Bl, KT, kg);
        __syncthreads();

#pragma unroll
        for (int kb = 0; kb < KC; kb += 16) {
            // A fragments for both 16-row groups, hi and lo
            uint32_t ah[2][4], al[2][4];
#pragma unroll
            for (int mf = 0; mf < 2; mf++) {
                int rb = mr + mf * 16;
                ah[mf][0] = *(const uint32_t*)(sAh + (rb + r) * SP + kb + cq);
                ah[mf][1] = *(const uint32_t*)(sAh + (rb + r + 8) * SP + kb + cq);
                ah[mf][2] = *(const uint32_t*)(sAh + (rb + r) * SP + kb + cq + 8);
                ah[mf][3] = *(const uint32_t*)(sAh + (rb + r + 8) * SP + kb + cq + 8);
                al[mf][0] = *(const uint32_t*)(sAl + (rb + r) * SP + kb + cq);
                al[mf][1] = *(const uint32_t*)(sAl + (rb + r + 8) * SP + kb + cq);
                al[mf][2] = *(const uint32_t*)(sAl + (rb + r) * SP + kb + cq + 8);
                al[mf][3] = *(const uint32_t*)(sAl + (rb + r + 8) * SP + kb + cq + 8);
            }
#pragma unroll
            for (int nt = 0; nt < 8; nt++) {
                int nr = nb + nt * 8 + r;
                uint32_t bh0 = *(const uint32_t*)(sBh + nr * SP + kb + cq);
                uint32_t bh1 = *(const uint32_t*)(sBh + nr * SP + kb + cq + 8);
                uint32_t bl0 = *(const uint32_t*)(sBl + nr * SP + kb + cq);
                uint32_t bl1 = *(const uint32_t*)(sBl + nr * SP + kb + cq + 8);
#pragma unroll
                for (int mf = 0; mf < 2; mf++) {
                    mma16816(acc[mf][nt], ah[mf], bh0, bh1);
                    mma16816(acc[mf][nt], ah[mf], bl0, bl1);
                    mma16816(acc[mf][nt], al[mf], bh0, bh1);
                }
            }
        }
        __syncthreads();
    }

    // epilogue: acc -> zpart (row-major 128x128 fp32 per (ks,tile))
    float* zp = g_zpart + (size_t)(ks * NT + tile) * (BATCH * 128);
#pragma unroll
    for (int mf = 0; mf < 2; mf++) {
#pragma unroll
        for (int nt = 0; nt < 8; nt++) {
            int row0 = mr + mf * 16 + r;
            int col = nb + nt * 8 + cq;
            *(float2*)(zp + (size_t)row0 * 128 + col) =
                make_float2(acc[mf][nt][0], acc[mf][nt][1]);
            *(float2*)(zp + (size_t)(row0 + 8) * 128 + col) =
                make_float2(acc[mf][nt][2], acc[mf][nt][3]);
        }
    }
}

// ---------------- gate phase ----------------------------------------------------
template <int LAYER>
__device__ void gate_phase(const float* __restrict__ bias, int t, int gid)
{
    float* cs = (LAYER == 1) ? g_c1 : g_c2;
    __nv_bfloat16* hh_ = (LAYER == 1) ? g_h1_hi : g_h2_hi;
    __nv_bfloat16* hl_ = (LAYER == 1) ? g_h1_lo : g_h2_lo;

#pragma unroll
    for (int e = 0; e < (BATCH * HID) / (NBLK * NTHR); e++) {
        int idx = gid + e * (NBLK * NTHR);
        int b  = idx >> 10;
        int hg = idx & (HID - 1);
        int tile = hg >> 5;
        int hh = hg & 31;

        float zi = 0.f, zj = 0.f, zf = 0.f, zo = 0.f;
#pragma unroll
        for (int s = 0; s < KS; s++) {
            const float* z = g_zpart + ((size_t)s * NT + tile) * (BATCH * 128)
                           + (size_t)b * 128;
            zi += z[hh]; zj += z[32 + hh]; zf += z[64 + hh]; zo += z[96 + hh];
        }
        zi += bias[hg];
        zj += bias[HID + hg];
        zf += bias[2 * HID + hg];
        zo += bias[3 * HID + hg];

        float cp = cs[idx];
        float fg = sigm(zf + 1.0f);
        float ig = sigm(zi);
        float jg = tanhf(zj);
        float og = sigm(zo);
        float cn = cp * fg + ig * jg;
        float hn = tanhf(cn) * og;
        cs[idx] = cn;
        __nv_bfloat16 bh = __float2bfloat16(hn);
        hh_[idx] = bh;
        hl_[idx] = __float2bfloat16(hn - __bfloat162float(bh));
        if (LAYER == 2)
            g_h2all[(size_t)t * BATCH * HID + idx] = hn;
    }
}

// ---------------- persistent recurrence kernel ----------------------------------
__global__ __launch_bounds__(NTHR, 1) void lstm_mma_kernel(
    const float* __restrict__ b1, const float* __restrict__ b2)
{
    __shared__ __align__(16) __nv_bfloat16 sAh[128 * SP];
    __shared__ __align__(16) __nv_bfloat16 sAl[128 * SP];
    __shared__ __align__(16) __nv_bfloat16 sBh[128 * SP];
    __shared__ __align__(16) __nv_bfloat16 sBl[128 * SP];

    int bid = blockIdx.x;
    int tile = bid & 31, ks = bid >> 5;
    int gid = bid * NTHR + threadIdx.x;

    __nv_bfloat16 z16 = __float2bfloat16(0.f);
    for (int i = gid; i < BATCH * HID; i += NBLK * NTHR) {
        g_c1[i] = 0.f; g_c2[i] = 0.f;
        g_h1_hi[i] = z16; g_h1_lo[i] = z16;
        g_h2_hi[i] = z16; g_h2_lo[i] = z16;
    }
    grid_barrier();

    for (int t = 0; t < T_STEPS; t++) {
        gemm_phase_mma<1>(t, ks, tile, sAh, sAl, sBh, sBl);
        grid_barrier();
        gate_phase<1>(b1, t, gid);
        grid_barrier();
        gemm_phase_mma<2>(t, ks, tile, sAh, sAl, sBh, sBl);
        grid_barrier();
        gate_phase<2>(b2, t, gid);
        grid_barrier();
    }
}

// ---------------- epilog --------------------------------------------------------
__global__ __launch_bounds__(256) void logits_kernel(
    const float* __restrict__ W, const float* __restrict__ bias)
{
    int mt = blockIdx.x;
    __shared__ __align__(16) float As[16][128];
    __shared__ __align__(16) float Bs[16][128];
    int tid = threadIdx.x;
    int tx = tid & 15, ty = tid >> 4;
    float acc[8][8];
#pragma unroll
    for (int i = 0; i < 8; i++)
#pragma unroll
        for (int j = 0; j < 8; j++) acc[i][j] = 0.f;

    const float* Ab = g_h2all + (size_t)mt * 128 * HID;

    for (int k0 = 0; k0 < HID; k0 += 16) {
#pragma unroll
        for (int r = 0; r < 2; r++) {
            int p = tid + r * 256;
            int m = p >> 2, kq = (p & 3) * 4;
            float4 v = *(const float4*)(Ab + (size_t)m * HID + k0 + kq);
            As[kq + 0][m] = v.x; As[kq + 1][m] = v.y;
            As[kq + 2][m] = v.z; As[kq + 3][m] = v.w;
        }
#pragma unroll
        for (int r = 0; r < 2; r++) {
            int p = tid + r * 256;
            int kk = p >> 5, c4 = (p & 31) * 4;
            float4 v = *(const float4*)(W + (size_t)(k0 + kk) * DIM + c4);
            *(float4*)&Bs[kk][c4] = v;
        }
        __syncthreads();
#pragma unroll
        for (int k = 0; k < 16; k++) {
            float4 a0 = *(const float4*)&As[k][ty * 4];
            float4 a1 = *(const float4*)&As[k][ty * 4 + 64];
            float4 b0 = *(const float4*)&Bs[k][tx * 4];
            float4 b1 = *(const float4*)&Bs[k][tx * 4 + 64];
            float av[8] = {a0.x, a0.y, a0.z, a0.w, a1.x, a1.y, a1.z, a1.w};
            float bv[8] = {b0.x, b0.y, b0.z, b0.w, b1.x, b1.y, b1.z, b1.w};
#pragma unroll
            for (int i = 0; i < 8; i++)
#pragma unroll
                for (int j = 0; j < 8; j++)
                    acc[i][j] = fmaf(av[i], bv[j], acc[i][j]);
        }
        __syncthreads();
    }

#pragma unroll
    for (int i = 0; i < 8; i++) {
        int m = (i < 4) ? (ty * 4 + i) : (64 + ty * 4 + i - 4);
        float* orow = g_logits + (size_t)(mt * 128 + m) * DIM;
        int c0 = tx * 4;
        float4 o0, o1;
        o0.x = acc[i][0] + bias[c0 + 0];
        o0.y = acc[i][1] + bias[c0 + 1];
        o0.z = acc[i][2] + bias[c0 + 2];
        o0.w = acc[i][3] + bias[c0 + 3];
        o1.x = acc[i][4] + bias[c0 + 64];
        o1.y = acc[i][5] + bias[c0 + 65];
        o1.z = acc[i][6] + bias[c0 + 66];
        o1.w = acc[i][7] + bias[c0 + 67];
        *(float4*)(orow + c0) = o0;
        *(float4*)(orow + c0 + 64) = o1;
    }
}

__global__ __launch_bounds__(256) void softmax_ce_kernel(
    const int* __restrict__ tgt, float* __restrict__ probs)
{
    int warp = (blockIdx.x * blockDim.x + threadIdx.x) >> 5;
    int lane = threadIdx.x & 31;
    if (warp >= T_STEPS * BATCH) return;
    const float* row = g_logits + (size_t)warp * 128;
    float v0 = row[lane], v1 = row[lane + 32], v2 = row[lane + 64], v3 = row[lane + 96];

    float m_mel = fmaxf(v0, lane < 16 ? v1 : -1e30f);
#pragma unroll
    for (int o = 16; o; o >>= 1) m_mel = fmaxf(m_mel, __shfl_xor_sync(~0u, m_mel, o));
    float e0 = __expf(v0 - m_mel);
    float e1m = (lane < 16) ? __expf(v1 - m_mel) : 0.f;
    float s_mel = e0 + e1m;
#pragma unroll
    for (int o = 16; o; o >>= 1) s_mel += __shfl_xor_sync(~0u, s_mel, o);

    float m_har = fmaxf(fmaxf(v2, v3), lane >= 16 ? v1 : -1e30f);
#pragma unroll
    for (int o = 16; o; o >>= 1) m_har = fmaxf(m_har, __shfl_xor_sync(~0u, m_har, o));
    float e1h = (lane >= 16) ? __expf(v1 - m_har) : 0.f;
    float e2 = __expf(v2 - m_har);
    float e3 = __expf(v3 - m_har);
    float s_har = e1h + e2 + e3;
#pragma unroll
    for (int o = 16; o; o >>= 1) s_har += __shfl_xor_sync(~0u, s_har, o);

    float inv_mel = 1.0f / s_mel;
    float inv_har = 1.0f / s_har;
    float* pr = probs + (size_t)warp * 128;
    pr[lane]      = e0 * inv_mel;
    pr[lane + 32] = (lane < 16) ? e1m * inv_mel : e1h * inv_har;
    pr[lane + 64] = e2 * inv_har;
    pr[lane + 96] = e3 * inv_har;

    if (lane == 0) {
        int t0 = tgt[warp * 2 + 0];
        int t1 = tgt[warp * 2 + 1];
        t0 = min(max(t0, 0), 47);
        t1 = min(max(t1, 0), 79);
        float l0 = row[t0];
        float l1 = row[48 + t1];
        float lse_mel = m_mel + logf(s_mel);
        float lse_har = m_har + logf(s_har);
        g_lossbuf[warp] = 0.5f * (lse_mel - l0) + 0.5f * (lse_har - l1);
    }
}

__global__ __launch_bounds__(256) void loss_reduce_kernel(float* __restrict__ out)
{
    __shared__ float sm[256];
    float s = 0.f;
    for (int i = threadIdx.x; i < T_STEPS * BATCH; i += 256) s += g_lossbuf[i];
    sm[threadIdx.x] = s;
    __syncthreads();
    for (int o = 128; o; o >>= 1) {
        if (threadIdx.x < o) sm[threadIdx.x] += sm[threadIdx.x + o];
        __syncthreads();
    }
    if (threadIdx.x == 0)
        out[0] = sm[0] / (float)(T_STEPS * BATCH);
}

// ---------------- launch --------------------------------------------------------
extern "C" void kernel_launch(void* const* d_in, const int* in_sizes, int n_in,
                              void* d_out, int out_size)
{
    const float* inSeq = (const float*)d_in[0];
    const int*   tgt   = (const int*)d_in[1];
    const float* W1    = (const float*)d_in[2];
    const float* b1    = (const float*)d_in[3];
    const float* W2    = (const float*)d_in[4];
    const float* b2    = (const float*)d_in[5];
    const float* outW  = (const float*)d_in[6];
    const float* outB  = (const float*)d_in[7];
    float* out = (float*)d_out;

    conv_x_kernel<<<(T_STEPS * BATCH * DIM) / 256, 256>>>(inSeq);
    conv_w1_kernel<<<(int)(((size_t)KT1 * G4 + 255) / 256), 256>>>(W1);
    conv_w2_kernel<<<(int)(((size_t)KT2 * G4 + 255) / 256), 256>>>(W2);

    lstm_mma_kernel<<<NBLK, NTHR>>>(b1, b2);

    logits_kernel<<<(T_STEPS * BATCH) / 128, 256>>>(outW, outB);
    softmax_ce_kernel<<<(T_STEPS * BATCH * 32) / 256, 256>>>(tgt, out);
    loss_reduce_kernel<<<1, 256>>>(out + (out_size - 1));
}

// round 11
// speedup vs baseline: 2.0728x; 1.1105x over previous
#include <cuda_runtime.h>
#include <cuda_bf16.h>
#include <math.h>
#include <stdint.h>

#define T_STEPS 256
#define BATCH   128
#define DIM     128
#define HID     1024
#define G4      4096
#define NT      32        // weight tiles per layer (128 z-cols each)
#define KS      4         // split-K
#define NBLK    128
#define NTHR    256
#define KT1     1152      // DIM + HID
#define KT2     2048      // 2*HID
#define KC      32        // k per smem chunk
#define SP      40        // smem row stride (bf16) — conflict-free for LDSM
#define TILE_B  (128 * SP * 2)          // bytes per tile
#define STAGE_B (4 * TILE_B)            // Ah, Al, Bh, Bl
#define DSMEM_B (2 * STAGE_B)           // 2 pipeline stages = 81920

// ---------------- fp32 scratch -------------------------------------------------
__device__ __align__(16) float g_h2all[(size_t)T_STEPS * BATCH * HID];
__device__ __align__(16) float g_logits[(size_t)T_STEPS * BATCH * DIM];
__device__ __align__(16) float g_zpart[(size_t)KS * NT * BATCH * 128];
__device__ __align__(16) float g_c1[BATCH * HID];
__device__ __align__(16) float g_c2[BATCH * HID];
__device__ __align__(16) float g_lossbuf[T_STEPS * BATCH];
__device__ volatile unsigned g_bar_gen;
__device__ unsigned g_bar_cnt;

// ---------------- bf16 split operands ------------------------------------------
__device__ __align__(16) __nv_bfloat16 g_x_hi[(size_t)T_STEPS * BATCH * DIM];
__device__ __align__(16) __nv_bfloat16 g_x_lo[(size_t)T_STEPS * BATCH * DIM];
__device__ __align__(16) __nv_bfloat16 g_w1_hi[(size_t)G4 * KT1];
__device__ __align__(16) __nv_bfloat16 g_w1_lo[(size_t)G4 * KT1];
__device__ __align__(16) __nv_bfloat16 g_w2_hi[(size_t)G4 * KT2];
__device__ __align__(16) __nv_bfloat16 g_w2_lo[(size_t)G4 * KT2];
__device__ __align__(16) __nv_bfloat16 g_h1_hi[BATCH * HID];
__device__ __align__(16) __nv_bfloat16 g_h1_lo[BATCH * HID];
__device__ __align__(16) __nv_bfloat16 g_h2_hi[BATCH * HID];
__device__ __align__(16) __nv_bfloat16 g_h2_lo[BATCH * HID];

__device__ __forceinline__ float sigm(float x) { return 1.0f / (1.0f + __expf(-x)); }

__device__ __forceinline__ uint32_t smem_u32(const void* p) {
    uint32_t a;
    asm("{ .reg .u64 t; cvta.to.shared.u64 t, %1; cvt.u32.u64 %0, t; }" : "=r"(a) : "l"(p));
    return a;
}

// ---------------- mma.sync m16n8k16 bf16 ----------------------------------------
__device__ __forceinline__ void mma16816(float* c, const uint32_t* a,
                                         uint32_t b0, uint32_t b1) {
    asm("mma.sync.aligned.m16n8k16.row.col.f32.bf16.bf16.f32 "
        "{%0,%1,%2,%3}, {%4,%5,%6,%7}, {%8,%9}, {%0,%1,%2,%3};"
        : "+f"(c[0]), "+f"(c[1]), "+f"(c[2]), "+f"(c[3])
        : "r"(a[0]), "r"(a[1]), "r"(a[2]), "r"(a[3]), "r"(b0), "r"(b1));
}

__device__ __forceinline__ void ldsm4(uint32_t* r, uint32_t a) {
    asm volatile("ldmatrix.sync.aligned.m8n8.x4.shared.b16 {%0,%1,%2,%3}, [%4];"
                 : "=r"(r[0]), "=r"(r[1]), "=r"(r[2]), "=r"(r[3]) : "r"(a));
}

// ---------------- grid-wide barrier ---------------------------------------------
__device__ __forceinline__ void grid_barrier() {
    __syncthreads();
    __threadfence();
    if (threadIdx.x == 0) {
        unsigned gen = g_bar_gen;
        if (atomicAdd(&g_bar_cnt, 1u) == NBLK - 1) {
            g_bar_cnt = 0;
            __threadfence();
            g_bar_gen = gen + 1;
        } else {
            while (g_bar_gen == gen) { __nanosleep(32); }
        }
    }
    __syncthreads();
}

// ---------------- conversion prolog kernels -------------------------------------
__global__ __launch_bounds__(256) void conv_x_kernel(const float* __restrict__ x) {
    size_t i = (size_t)blockIdx.x * 256 + threadIdx.x;
    float v = x[i];
    __nv_bfloat16 h = __float2bfloat16(v);
    g_x_hi[i] = h;
    g_x_lo[i] = __float2bfloat16(v - __bfloat162float(h));
}

__global__ __launch_bounds__(256) void conv_w1_kernel(const float* __restrict__ W) {
    size_t i = (size_t)blockIdx.x * 256 + threadIdx.x;
    if (i >= (size_t)KT1 * G4) return;
    int np = (int)(i & (G4 - 1));
    int k  = (int)(i >> 12);
    int tile = np >> 7, r = np & 127;
    int col = (r >> 5) * HID + tile * 32 + (r & 31);
    float v = W[(size_t)k * G4 + col];
    __nv_bfloat16 h = __float2bfloat16(v);
    g_w1_hi[(size_t)np * KT1 + k] = h;
    g_w1_lo[(size_t)np * KT1 + k] = __float2bfloat16(v - __bfloat162float(h));
}

__global__ __launch_bounds__(256) void conv_w2_kernel(const float* __restrict__ W) {
    size_t i = (size_t)blockIdx.x * 256 + threadIdx.x;
    if (i >= (size_t)KT2 * G4) return;
    int np = (int)(i & (G4 - 1));
    int k  = (int)(i >> 12);
    int tile = np >> 7, r = np & 127;
    int col = (r >> 5) * HID + tile * 32 + (r & 31);
    float v = W[(size_t)k * G4 + col];
    __nv_bfloat16 h = __float2bfloat16(v);
    g_w2_hi[(size_t)np * KT2 + k] = h;
    g_w2_lo[(size_t)np * KT2 + k] = __float2bfloat16(v - __bfloat162float(h));
}

// ---------------- cp.async tile copy: 128 rows x 32 bf16 -> smem ----------------
__device__ __forceinline__ void cp_tile(uint32_t dst,
                                        const __nv_bfloat16* __restrict__ src,
                                        int lda, int koff) {
    int tid = threadIdx.x;
#pragma unroll
    for (int q = 0; q < 2; q++) {
        int i = tid + q * 256;          // [0,512): 16B chunks
        int row = i >> 2, c = i & 3;
        uint32_t d = dst + (uint32_t)(row * SP + c * 8) * 2;
        const void* s = src + (size_t)row * lda + koff + c * 8;
        asm volatile("cp.async.cg.shared.global [%0], [%1], 16;" :: "r"(d), "l"(s));
    }
}

// issue one chunk's 4 tiles + commit (one cp.async group per chunk)
template <int LAYER>
__device__ __forceinline__ void load_chunk(uint32_t stg, int t, int kg) {
    constexpr int KT = (LAYER == 1) ? KT1 : KT2;
    constexpr int XD = (LAYER == 1) ? DIM : HID;
    const __nv_bfloat16 *Ah, *Al;
    int lda, koff;
    if (LAYER == 1) {
        if (kg < XD) { Ah = g_x_hi; Al = g_x_lo; lda = DIM; koff = kg;
                       Ah += (size_t)t * BATCH * DIM; Al += (size_t)t * BATCH * DIM; }
        else         { Ah = g_h1_hi; Al = g_h1_lo; lda = HID; koff = kg - XD; }
    } else {
        if (kg < XD) { Ah = g_h1_hi; Al = g_h1_lo; lda = HID; koff = kg; }
        else         { Ah = g_h2_hi; Al = g_h2_lo; lda = HID; koff = kg - XD; }
    }
    cp_tile(stg,              Ah, lda, koff);
    cp_tile(stg + TILE_B,     Al, lda, koff);
    asm volatile("cp.async.commit_group;" ::: "memory");   // split groups: A then B
    // B tiles belong to same chunk; put in same logical group by committing once.
}

// ---------------- tensor GEMM phase (pipelined, ldmatrix) -----------------------
template <int LAYER>
__device__ void gemm_phase_mma(int t, int ks, int tile, uint32_t smbase,
                               const __nv_bfloat16* __restrict__ Bh,
                               const __nv_bfloat16* __restrict__ Bl)
{
    constexpr int KT  = (LAYER == 1) ? KT1 : KT2;
    constexpr int KSL = KT / KS;            // 288 / 512
    constexpr int NCH = KSL / KC;           // 9 / 16
    int kbase = ks * KSL;
    int tid = threadIdx.x;
    int w = tid >> 5, lane = tid & 31;
    int mr = (w >> 1) * 32;                 // warp row base
    int nb = (w & 1) * 64;                  // warp col base
    int r = lane >> 2, cq = (lane & 3) * 2; // mma accumulator coords
    int j = lane >> 3, i5 = lane & 7;       // ldmatrix lane coords

    // ldmatrix per-lane offsets (bytes): A: row=(j&1)*8+i, kcol=(j>>1)*8
    //                                    B: row=(j>>1)*8+i, kcol=(j&1)*8
    uint32_t offA = (uint32_t)(((j & 1) * 8 + i5) * SP + (j >> 1) * 8) * 2;
    uint32_t offB = (uint32_t)(((j >> 1) * 8 + i5) * SP + (j & 1) * 8) * 2;

    float acc[2][8][4];
#pragma unroll
    for (int a = 0; a < 2; a++)
#pragma unroll
        for (int n = 0; n < 8; n++)
#pragma unroll
            for (int q = 0; q < 4; q++) acc[a][n][q] = 0.f;

    // prologue: load chunk 0 into stage 0
    {
        uint32_t stg = smbase;
        load_chunk<LAYER>(stg, t, kbase);
        cp_tile(stg + 2 * TILE_B, Bh, KT, kbase);
        cp_tile(stg + 3 * TILE_B, Bl, KT, kbase);
        asm volatile("cp.async.commit_group;" ::: "memory");
    }

    for (int c = 0; c < NCH; c++) {
        asm volatile("cp.async.wait_group 0;" ::: "memory");
        __syncthreads();    // chunk c resident; all compute on other stage done

        if (c + 1 < NCH) {  // issue chunk c+1 into other stage (overlaps compute)
            uint32_t stg = smbase + ((c + 1) & 1) * STAGE_B;
            int kg = kbase + (c + 1) * KC;
            load_chunk<LAYER>(stg, t, kg);
            cp_tile(stg + 2 * TILE_B, Bh, KT, kg);
            cp_tile(stg + 3 * TILE_B, Bl, KT, kg);
            asm volatile("cp.async.commit_group;" ::: "memory");
        }

        uint32_t stg = smbase + (c & 1) * STAGE_B;
        uint32_t uAh = stg, uAl = stg + TILE_B;
        uint32_t uBh = stg + 2 * TILE_B, uBl = stg + 3 * TILE_B;

#pragma unroll
        for (int kb = 0; kb < KC; kb += 16) {
            uint32_t ah[2][4], al[2][4];
            ldsm4(ah[0], uAh + (uint32_t)(mr * SP + kb) * 2 + offA);
            ldsm4(ah[1], uAh + (uint32_t)((mr + 16) * SP + kb) * 2 + offA);
            ldsm4(al[0], uAl + (uint32_t)(mr * SP + kb) * 2 + offA);
            ldsm4(al[1], uAl + (uint32_t)((mr + 16) * SP + kb) * 2 + offA);
#pragma unroll
            for (int p = 0; p < 4; p++) {
                int nbase = nb + p * 16;
                uint32_t bh[4], bl[4];
                ldsm4(bh, uBh + (uint32_t)(nbase * SP + kb) * 2 + offB);
                ldsm4(bl, uBl + (uint32_t)(nbase * SP + kb) * 2 + offB);
#pragma unroll
                for (int mf = 0; mf < 2; mf++) {
                    mma16816(acc[mf][p * 2],     ah[mf], bh[0], bh[1]);
                    mma16816(acc[mf][p * 2],     ah[mf], bl[0], bl[1]);
                    mma16816(acc[mf][p * 2],     al[mf], bh[0], bh[1]);
                    mma16816(acc[mf][p * 2 + 1], ah[mf], bh[2], bh[3]);
                    mma16816(acc[mf][p * 2 + 1], ah[mf], bl[2], bl[3]);
                    mma16816(acc[mf][p * 2 + 1], al[mf], bh[2], bh[3]);
                }
            }
        }
        __syncthreads();    // compute done before next iteration's cp overwrites
    }

    // epilogue: acc -> zpart
    float* zp = g_zpart + (size_t)(ks * NT + tile) * (BATCH * 128);
#pragma unroll
    for (int mf = 0; mf < 2; mf++) {
#pragma unroll
        for (int nt = 0; nt < 8; nt++) {
            int row0 = mr + mf * 16 + r;
            int col = nb + nt * 8 + cq;
            *(float2*)(zp + (size_t)row0 * 128 + col) =
                make_float2(acc[mf][nt][0], acc[mf][nt][1]);
            *(float2*)(zp + (size_t)(row0 + 8) * 128 + col) =
                make_float2(acc[mf][nt][2], acc[mf][nt][3]);
        }
    }
}

// ---------------- gate phase ----------------------------------------------------
template <int LAYER>
__device__ void gate_phase(const float* __restrict__ bias, int t, int gid)
{
    float* cs = (LAYER == 1) ? g_c1 : g_c2;
    __nv_bfloat16* hh_ = (LAYER == 1) ? g_h1_hi : g_h2_hi;
    __nv_bfloat16* hl_ = (LAYER == 1) ? g_h1_lo : g_h2_lo;

#pragma unroll
    for (int e = 0; e < (BATCH * HID) / (NBLK * NTHR); e++) {
        int idx = gid + e * (NBLK * NTHR);
        int b  = idx >> 10;
        int hg = idx & (HID - 1);
        int tile = hg >> 5;
        int hh = hg & 31;

        float zi = 0.f, zj = 0.f, zf = 0.f, zo = 0.f;
#pragma unroll
        for (int s = 0; s < KS; s++) {
            const float* z = g_zpart + ((size_t)s * NT + tile) * (BATCH * 128)
                           + (size_t)b * 128;
            zi += z[hh]; zj += z[32 + hh]; zf += z[64 + hh]; zo += z[96 + hh];
        }
        zi += bias[hg];
        zj += bias[HID + hg];
        zf += bias[2 * HID + hg];
        zo += bias[3 * HID + hg];

        float cp = cs[idx];
        float fg = sigm(zf + 1.0f);
        float ig = sigm(zi);
        float jg = tanhf(zj);
        float og = sigm(zo);
        float cn = cp * fg + ig * jg;
        float hn = tanhf(cn) * og;
        cs[idx] = cn;
        __nv_bfloat16 bh = __float2bfloat16(hn);
        hh_[idx] = bh;
        hl_[idx] = __float2bfloat16(hn - __bfloat162float(bh));
        if (LAYER == 2)
            g_h2all[(size_t)t * BATCH * HID + idx] = hn;
    }
}

// ---------------- persistent recurrence kernel ----------------------------------
__global__ __launch_bounds__(NTHR, 1) void lstm_mma_kernel(
    const float* __restrict__ b1, const float* __restrict__ b2)
{
    extern __shared__ __align__(16) char dsm[];
    uint32_t smbase = smem_u32(dsm);

    int bid = blockIdx.x;
    int tile = bid & 31, ks = bid >> 5;
    int gid = bid * NTHR + threadIdx.x;

    const __nv_bfloat16* B1h = g_w1_hi + (size_t)tile * 128 * KT1;
    const __nv_bfloat16* B1l = g_w1_lo + (size_t)tile * 128 * KT1;
    const __nv_bfloat16* B2h = g_w2_hi + (size_t)tile * 128 * KT2;
    const __nv_bfloat16* B2l = g_w2_lo + (size_t)tile * 128 * KT2;

    __nv_bfloat16 z16 = __float2bfloat16(0.f);
    for (int i = gid; i < BATCH * HID; i += NBLK * NTHR) {
        g_c1[i] = 0.f; g_c2[i] = 0.f;
        g_h1_hi[i] = z16; g_h1_lo[i] = z16;
        g_h2_hi[i] = z16; g_h2_lo[i] = z16;
    }
    grid_barrier();

    for (int t = 0; t < T_STEPS; t++) {
        gemm_phase_mma<1>(t, ks, tile, smbase, B1h, B1l);
        grid_barrier();
        gate_phase<1>(b1, t, gid);
        grid_barrier();
        gemm_phase_mma<2>(t, ks, tile, smbase, B2h, B2l);
        grid_barrier();
        gate_phase<2>(b2, t, gid);
        grid_barrier();
    }
}

// ---------------- epilog --------------------------------------------------------
__global__ __launch_bounds__(256) void logits_kernel(
    const float* __restrict__ W, const float* __restrict__ bias)
{
    int mt = blockIdx.x;
    __shared__ __align__(16) float As[16][128];
    __shared__ __align__(16) float Bs[16][128];
    int tid = threadIdx.x;
    int tx = tid & 15, ty = tid >> 4;
    float acc[8][8];
#pragma unroll
    for (int i = 0; i < 8; i++)
#pragma unroll
        for (int j = 0; j < 8; j++) acc[i][j] = 0.f;

    const float* Ab = g_h2all + (size_t)mt * 128 * HID;

    for (int k0 = 0; k0 < HID; k0 += 16) {
#pragma unroll
        for (int r = 0; r < 2; r++) {
            int p = tid + r * 256;
            int m = p >> 2, kq = (p & 3) * 4;
            float4 v = *(const float4*)(Ab + (size_t)m * HID + k0 + kq);
            As[kq + 0][m] = v.x; As[kq + 1][m] = v.y;
            As[kq + 2][m] = v.z; As[kq + 3][m] = v.w;
        }
#pragma unroll
        for (int r = 0; r < 2; r++) {
            int p = tid + r * 256;
            int kk = p >> 5, c4 = (p & 31) * 4;
            float4 v = *(const float4*)(W + (size_t)(k0 + kk) * DIM + c4);
            *(float4*)&Bs[kk][c4] = v;
        }
        __syncthreads();
#pragma unroll
        for (int k = 0; k < 16; k++) {
            float4 a0 = *(const float4*)&As[k][ty * 4];
            float4 a1 = *(const float4*)&As[k][ty * 4 + 64];
            float4 b0 = *(const float4*)&Bs[k][tx * 4];
            float4 b1 = *(const float4*)&Bs[k][tx * 4 + 64];
            float av[8] = {a0.x, a0.y, a0.z, a0.w, a1.x, a1.y, a1.z, a1.w};
            float bv[8] = {b0.x, b0.y, b0.z, b0.w, b1.x, b1.y, b1.z, b1.w};
#pragma unroll
            for (int i = 0; i < 8; i++)
#pragma unroll
                for (int j = 0; j < 8; j++)
                    acc[i][j] = fmaf(av[i], bv[j], acc[i][j]);
        }
        __syncthreads();
    }

#pragma unroll
    for (int i = 0; i < 8; i++) {
        int m = (i < 4) ? (ty * 4 + i) : (64 + ty * 4 + i - 4);
        float* orow = g_logits + (size_t)(mt * 128 + m) * DIM;
        int c0 = tx * 4;
        float4 o0, o1;
        o0.x = acc[i][0] + bias[c0 + 0];
        o0.y = acc[i][1] + bias[c0 + 1];
        o0.z = acc[i][2] + bias[c0 + 2];
        o0.w = acc[i][3] + bias[c0 + 3];
        o1.x = acc[i][4] + bias[c0 + 64];
        o1.y = acc[i][5] + bias[c0 + 65];
        o1.z = acc[i][6] + bias[c0 + 66];
        o1.w = acc[i][7] + bias[c0 + 67];
        *(float4*)(orow + c0) = o0;
        *(float4*)(orow + c0 + 64) = o1;
    }
}

__global__ __launch_bounds__(256) void softmax_ce_kernel(
    const int* __restrict__ tgt, float* __restrict__ probs)
{
    int warp = (blockIdx.x * blockDim.x + threadIdx.x) >> 5;
    int lane = threadIdx.x & 31;
    if (warp >= T_STEPS * BATCH) return;
    const float* row = g_logits + (size_t)warp * 128;
    float v0 = row[lane], v1 = row[lane + 32], v2 = row[lane + 64], v3 = row[lane + 96];

    float m_mel = fmaxf(v0, lane < 16 ? v1 : -1e30f);
#pragma unroll
    for (int o = 16; o; o >>= 1) m_mel = fmaxf(m_mel, __shfl_xor_sync(~0u, m_mel, o));
    float e0 = __expf(v0 - m_mel);
    float e1m = (lane < 16) ? __expf(v1 - m_mel) : 0.f;
    float s_mel = e0 + e1m;
#pragma unroll
    for (int o = 16; o; o >>= 1) s_mel += __shfl_xor_sync(~0u, s_mel, o);

    float m_har = fmaxf(fmaxf(v2, v3), lane >= 16 ? v1 : -1e30f);
#pragma unroll
    for (int o = 16; o; o >>= 1) m_har = fmaxf(m_har, __shfl_xor_sync(~0u, m_har, o));
    float e1h = (lane >= 16) ? __expf(v1 - m_har) : 0.f;
    float e2 = __expf(v2 - m_har);
    float e3 = __expf(v3 - m_har);
    float s_har = e1h + e2 + e3;
#pragma unroll
    for (int o = 16; o; o >>= 1) s_har += __shfl_xor_sync(~0u, s_har, o);

    float inv_mel = 1.0f / s_mel;
    float inv_har = 1.0f / s_har;
    float* pr = probs + (size_t)warp * 128;
    pr[lane]      = e0 * inv_mel;
    pr[lane + 32] = (lane < 16) ? e1m * inv_mel : e1h * inv_har;
    pr[lane + 64] = e2 * inv_har;
    pr[lane + 96] = e3 * inv_har;

    if (lane == 0) {
        int t0 = tgt[warp * 2 + 0];
        int t1 = tgt[warp * 2 + 1];
        t0 = min(max(t0, 0), 47);
        t1 = min(max(t1, 0), 79);
        float l0 = row[t0];
        float l1 = row[48 + t1];
        float lse_mel = m_mel + logf(s_mel);
        float lse_har = m_har + logf(s_har);
        g_lossbuf[warp] = 0.5f * (lse_mel - l0) + 0.5f * (lse_har - l1);
    }
}

__global__ __launch_bounds__(256) void loss_reduce_kernel(float* __restrict__ out)
{
    __shared__ float sm[256];
    float s = 0.f;
    for (int i = threadIdx.x; i < T_STEPS * BATCH; i += 256) s += g_lossbuf[i];
    sm[threadIdx.x] = s;
    __syncthreads();
    for (int o = 128; o; o >>= 1) {
        if (threadIdx.x < o) sm[threadIdx.x] += sm[threadIdx.x + o];
        __syncthreads();
    }
    if (threadIdx.x == 0)
        out[0] = sm[0] / (float)(T_STEPS * BATCH);
}

// ---------------- launch --------------------------------------------------------
extern "C" void kernel_launch(void* const* d_in, const int* in_sizes, int n_in,
                              void* d_out, int out_size)
{
    const float* inSeq = (const float*)d_in[0];
    const int*   tgt   = (const int*)d_in[1];
    const float* W1    = (const float*)d_in[2];
    const float* b1    = (const float*)d_in[3];
    const float* W2    = (const float*)d_in[4];
    const float* b2    = (const float*)d_in[5];
    const float* outW  = (const float*)d_in[6];
    const float* outB  = (const float*)d_in[7];
    float* out = (float*)d_out;

    cudaFuncSetAttribute(lstm_mma_kernel,
                         cudaFuncAttributeMaxDynamicSharedMemorySize, DSMEM_B);

    conv_x_kernel<<<(T_STEPS * BATCH * DIM) / 256, 256>>>(inSeq);
    conv_w1_kernel<<<(int)(((size_t)KT1 * G4 + 255) / 256), 256>>>(W1);
    conv_w2_kernel<<<(int)(((size_t)KT2 * G4 + 255) / 256), 256>>>(W2);

    lstm_mma_kernel<<<NBLK, NTHR, DSMEM_B>>>(b1, b2);

    logits_kernel<<<(T_STEPS * BATCH) / 128, 256>>>(outW, outB);
    softmax_ce_kernel<<<(T_STEPS * BATCH * 32) / 256, 256>>>(tgt, out);
    loss_reduce_kernel<<<1, 256>>>(out + (out_size - 1));
}

// round 12
// speedup vs baseline: 2.3474x; 1.1325x over previous
#include <cuda_runtime.h>
#include <cuda_bf16.h>
#include <math.h>
#include <stdint.h>

#define T_STEPS 256
#define BATCH   128
#define DIM     128
#define HID     1024
#define G4      4096
#define NT      32        // weight tiles per layer (128 z-cols each)
#define KS      4         // split-K
#define NBLK    128
#define NTHR    512       // 16 warps -> 4 per SMSP (latency hiding)
#define KT1     1152      // DIM + HID
#define KT2     2048      // 2*HID
#define KC      32        // k per smem chunk
#define SP      40        // smem row stride (bf16) — conflict-free for LDSM
#define TILE_B  (128 * SP * 2)          // bytes per tile
#define STAGE_B (4 * TILE_B)            // Ah, Al, Bh, Bl
#define DSMEM_B (2 * STAGE_B)           // 2 pipeline stages = 81920

// ---------------- fp32 scratch -------------------------------------------------
__device__ __align__(16) float g_h2all[(size_t)T_STEPS * BATCH * HID];
__device__ __align__(16) float g_logits[(size_t)T_STEPS * BATCH * DIM];
__device__ __align__(16) float g_zpart[(size_t)KS * NT * BATCH * 128];
__device__ __align__(16) float g_c1[BATCH * HID];
__device__ __align__(16) float g_c2[BATCH * HID];
__device__ __align__(16) float g_lossbuf[T_STEPS * BATCH];
__device__ volatile unsigned g_bar_gen;
__device__ unsigned g_bar_cnt;

// ---------------- bf16 split operands ------------------------------------------
__device__ __align__(16) __nv_bfloat16 g_x_hi[(size_t)T_STEPS * BATCH * DIM];
__device__ __align__(16) __nv_bfloat16 g_x_lo[(size_t)T_STEPS * BATCH * DIM];
__device__ __align__(16) __nv_bfloat16 g_w1_hi[(size_t)G4 * KT1];
__device__ __align__(16) __nv_bfloat16 g_w1_lo[(size_t)G4 * KT1];
__device__ __align__(16) __nv_bfloat16 g_w2_hi[(size_t)G4 * KT2];
__device__ __align__(16) __nv_bfloat16 g_w2_lo[(size_t)G4 * KT2];
__device__ __align__(16) __nv_bfloat16 g_h1_hi[BATCH * HID];
__device__ __align__(16) __nv_bfloat16 g_h1_lo[BATCH * HID];
__device__ __align__(16) __nv_bfloat16 g_h2_hi[BATCH * HID];
__device__ __align__(16) __nv_bfloat16 g_h2_lo[BATCH * HID];

__device__ __forceinline__ float sigm(float x) { return 1.0f / (1.0f + __expf(-x)); }

__device__ __forceinline__ uint32_t smem_u32(const void* p) {
    uint32_t a;
    asm("{ .reg .u64 t; cvta.to.shared.u64 t, %1; cvt.u32.u64 %0, t; }" : "=r"(a) : "l"(p));
    return a;
}

// ---------------- mma.sync m16n8k16 bf16 ----------------------------------------
__device__ __forceinline__ void mma16816(float* c, const uint32_t* a,
                                         uint32_t b0, uint32_t b1) {
    asm("mma.sync.aligned.m16n8k16.row.col.f32.bf16.bf16.f32 "
        "{%0,%1,%2,%3}, {%4,%5,%6,%7}, {%8,%9}, {%0,%1,%2,%3};"
        : "+f"(c[0]), "+f"(c[1]), "+f"(c[2]), "+f"(c[3])
        : "r"(a[0]), "r"(a[1]), "r"(a[2]), "r"(a[3]), "r"(b0), "r"(b1));
}

__device__ __forceinline__ void ldsm4(uint32_t* r, uint32_t a) {
    asm volatile("ldmatrix.sync.aligned.m8n8.x4.shared.b16 {%0,%1,%2,%3}, [%4];"
                 : "=r"(r[0]), "=r"(r[1]), "=r"(r[2]), "=r"(r[3]) : "r"(a));
}

// ---------------- grid-wide barrier ---------------------------------------------
__device__ __forceinline__ void grid_barrier() {
    __syncthreads();
    __threadfence();
    if (threadIdx.x == 0) {
        unsigned gen = g_bar_gen;
        if (atomicAdd(&g_bar_cnt, 1u) == NBLK - 1) {
            g_bar_cnt = 0;
            __threadfence();
            g_bar_gen = gen + 1;
        } else {
            while (g_bar_gen == gen) { __nanosleep(32); }
        }
    }
    __syncthreads();
}

// ---------------- conversion prolog kernels -------------------------------------
__global__ __launch_bounds__(256) void conv_x_kernel(const float* __restrict__ x) {
    size_t i = (size_t)blockIdx.x * 256 + threadIdx.x;
    float v = x[i];
    __nv_bfloat16 h = __float2bfloat16(v);
    g_x_hi[i] = h;
    g_x_lo[i] = __float2bfloat16(v - __bfloat162float(h));
}

__global__ __launch_bounds__(256) void conv_w1_kernel(const float* __restrict__ W) {
    size_t i = (size_t)blockIdx.x * 256 + threadIdx.x;
    if (i >= (size_t)KT1 * G4) return;
    int np = (int)(i & (G4 - 1));
    int k  = (int)(i >> 12);
    int tile = np >> 7, r = np & 127;
    int col = (r >> 5) * HID + tile * 32 + (r & 31);
    float v = W[(size_t)k * G4 + col];
    __nv_bfloat16 h = __float2bfloat16(v);
    g_w1_hi[(size_t)np * KT1 + k] = h;
    g_w1_lo[(size_t)np * KT1 + k] = __float2bfloat16(v - __bfloat162float(h));
}

__global__ __launch_bounds__(256) void conv_w2_kernel(const float* __restrict__ W) {
    size_t i = (size_t)blockIdx.x * 256 + threadIdx.x;
    if (i >= (size_t)KT2 * G4) return;
    int np = (int)(i & (G4 - 1));
    int k  = (int)(i >> 12);
    int tile = np >> 7, r = np & 127;
    int col = (r >> 5) * HID + tile * 32 + (r & 31);
    float v = W[(size_t)k * G4 + col];
    __nv_bfloat16 h = __float2bfloat16(v);
    g_w2_hi[(size_t)np * KT2 + k] = h;
    g_w2_lo[(size_t)np * KT2 + k] = __float2bfloat16(v - __bfloat162float(h));
}

// ---------------- cp.async tile copy: 128 rows x 32 bf16 -> smem ----------------
// 512 threads: exactly one 16B chunk per thread.
__device__ __forceinline__ void cp_tile(uint32_t dst,
                                        const __nv_bfloat16* __restrict__ src,
                                        int lda, int koff) {
    int i = threadIdx.x;            // [0,512)
    int row = i >> 2, c = i & 3;
    uint32_t d = dst + (uint32_t)(row * SP + c * 8) * 2;
    const void* s = src + (size_t)row * lda + koff + c * 8;
    asm volatile("cp.async.cg.shared.global [%0], [%1], 16;" :: "r"(d), "l"(s));
}

template <int LAYER>
__device__ __forceinline__ void load_chunk(uint32_t stg, int t, int kg) {
    constexpr int XD = (LAYER == 1) ? DIM : HID;
    const __nv_bfloat16 *Ah, *Al;
    int lda, koff;
    if (LAYER == 1) {
        if (kg < XD) { Ah = g_x_hi + (size_t)t * BATCH * DIM;
                       Al = g_x_lo + (size_t)t * BATCH * DIM; lda = DIM; koff = kg; }
        else         { Ah = g_h1_hi; Al = g_h1_lo; lda = HID; koff = kg - XD; }
    } else {
        if (kg < XD) { Ah = g_h1_hi; Al = g_h1_lo; lda = HID; koff = kg; }
        else         { Ah = g_h2_hi; Al = g_h2_lo; lda = HID; koff = kg - XD; }
    }
    cp_tile(stg,          Ah, lda, koff);
    cp_tile(stg + TILE_B, Al, lda, koff);
}

// ---------------- tensor GEMM phase (pipelined, ldmatrix, 16 warps) -------------
template <int LAYER>
__device__ void gemm_phase_mma(int t, int ks, int tile, uint32_t smbase,
                               const __nv_bfloat16* __restrict__ Bh,
                               const __nv_bfloat16* __restrict__ Bl)
{
    constexpr int KT  = (LAYER == 1) ? KT1 : KT2;
    constexpr int KSL = KT / KS;            // 288 / 512
    constexpr int NCH = KSL / KC;           // 9 / 16
    int kbase = ks * KSL;
    int tid = threadIdx.x;
    int w = tid >> 5, lane = tid & 31;
    int mr = (w >> 2) * 32;                 // warp row base (4 rowgroups)
    int nb = (w & 3) * 32;                  // warp col base (4 colgroups)
    int r = lane >> 2, cq = (lane & 3) * 2; // mma accumulator coords
    int j = lane >> 3, i5 = lane & 7;       // ldmatrix lane coords

    uint32_t offA = (uint32_t)(((j & 1) * 8 + i5) * SP + (j >> 1) * 8) * 2;
    uint32_t offB = (uint32_t)(((j >> 1) * 8 + i5) * SP + (j & 1) * 8) * 2;

    float acc[2][4][4];                     // [rowgroup16][n8][quad]
#pragma unroll
    for (int a = 0; a < 2; a++)
#pragma unroll
        for (int n = 0; n < 4; n++)
#pragma unroll
            for (int q = 0; q < 4; q++) acc[a][n][q] = 0.f;

    // prologue: load chunk 0 into stage 0
    {
        uint32_t stg = smbase;
        load_chunk<LAYER>(stg, t, kbase);
        cp_tile(stg + 2 * TILE_B, Bh, KT, kbase);
        cp_tile(stg + 3 * TILE_B, Bl, KT, kbase);
        asm volatile("cp.async.commit_group;" ::: "memory");
    }

    for (int c = 0; c < NCH; c++) {
        asm volatile("cp.async.wait_group 0;" ::: "memory");
        __syncthreads();

        if (c + 1 < NCH) {
            uint32_t stg = smbase + ((c + 1) & 1) * STAGE_B;
            int kg = kbase + (c + 1) * KC;
            load_chunk<LAYER>(stg, t, kg);
            cp_tile(stg + 2 * TILE_B, Bh, KT, kg);
            cp_tile(stg + 3 * TILE_B, Bl, KT, kg);
            asm volatile("cp.async.commit_group;" ::: "memory");
        }

        uint32_t stg = smbase + (c & 1) * STAGE_B;
        uint32_t uAh = stg, uAl = stg + TILE_B;
        uint32_t uBh = stg + 2 * TILE_B, uBl = stg + 3 * TILE_B;

#pragma unroll
        for (int kb = 0; kb < KC; kb += 16) {
            uint32_t ah[2][4], al[2][4];
            ldsm4(ah[0], uAh + (uint32_t)(mr * SP + kb) * 2 + offA);
            ldsm4(ah[1], uAh + (uint32_t)((mr + 16) * SP + kb) * 2 + offA);
            ldsm4(al[0], uAl + (uint32_t)(mr * SP + kb) * 2 + offA);
            ldsm4(al[1], uAl + (uint32_t)((mr + 16) * SP + kb) * 2 + offA);
#pragma unroll
            for (int p = 0; p < 2; p++) {   // two 16-col groups
                int nbase = nb + p * 16;
                uint32_t bh[4], bl[4];
                ldsm4(bh, uBh + (uint32_t)(nbase * SP + kb) * 2 + offB);
                ldsm4(bl, uBl + (uint32_t)(nbase * SP + kb) * 2 + offB);
#pragma unroll
                for (int mf = 0; mf < 2; mf++) {
                    mma16816(acc[mf][p * 2],     ah[mf], bh[0], bh[1]);
                    mma16816(acc[mf][p * 2],     ah[mf], bl[0], bl[1]);
                    mma16816(acc[mf][p * 2],     al[mf], bh[0], bh[1]);
                    mma16816(acc[mf][p * 2 + 1], ah[mf], bh[2], bh[3]);
                    mma16816(acc[mf][p * 2 + 1], ah[mf], bl[2], bl[3]);
                    mma16816(acc[mf][p * 2 + 1], al[mf], bh[2], bh[3]);
                }
            }
        }
        __syncthreads();
    }

    // epilogue: acc -> zpart
    float* zp = g_zpart + (size_t)(ks * NT + tile) * (BATCH * 128);
#pragma unroll
    for (int mf = 0; mf < 2; mf++) {
#pragma unroll
        for (int nt = 0; nt < 4; nt++) {
            int row0 = mr + mf * 16 + r;
            int col = nb + nt * 8 + cq;
            *(float2*)(zp + (size_t)row0 * 128 + col) =
                make_float2(acc[mf][nt][0], acc[mf][nt][1]);
            *(float2*)(zp + (size_t)(row0 + 8) * 128 + col) =
                make_float2(acc[mf][nt][2], acc[mf][nt][3]);
        }
    }
}

// ---------------- gate phase ----------------------------------------------------
template <int LAYER>
__device__ void gate_phase(const float* __restrict__ bias, int t, int gid)
{
    float* cs = (LAYER == 1) ? g_c1 : g_c2;
    __nv_bfloat16* hh_ = (LAYER == 1) ? g_h1_hi : g_h2_hi;
    __nv_bfloat16* hl_ = (LAYER == 1) ? g_h1_lo : g_h2_lo;

#pragma unroll
    for (int e = 0; e < (BATCH * HID) / (NBLK * NTHR); e++) {
        int idx = gid + e * (NBLK * NTHR);
        int b  = idx >> 10;
        int hg = idx & (HID - 1);
        int tile = hg >> 5;
        int hh = hg & 31;

        float zi = 0.f, zj = 0.f, zf = 0.f, zo = 0.f;
#pragma unroll
        for (int s = 0; s < KS; s++) {
            const float* z = g_zpart + ((size_t)s * NT + tile) * (BATCH * 128)
                           + (size_t)b * 128;
            zi += z[hh]; zj += z[32 + hh]; zf += z[64 + hh]; zo += z[96 + hh];
        }
        zi += bias[hg];
        zj += bias[HID + hg];
        zf += bias[2 * HID + hg];
        zo += bias[3 * HID + hg];

        float cp = cs[idx];
        float fg = sigm(zf + 1.0f);
        float ig = sigm(zi);
        float jg = tanhf(zj);
        float og = sigm(zo);
        float cn = cp * fg + ig * jg;
        float hn = tanhf(cn) * og;
        cs[idx] = cn;
        __nv_bfloat16 bh = __float2bfloat16(hn);
        hh_[idx] = bh;
        hl_[idx] = __float2bfloat16(hn - __bfloat162float(bh));
        if (LAYER == 2)
            g_h2all[(size_t)t * BATCH * HID + idx] = hn;
    }
}

// ---------------- persistent recurrence kernel ----------------------------------
__global__ __launch_bounds__(NTHR, 1) void lstm_mma_kernel(
    const float* __restrict__ b1, const float* __restrict__ b2)
{
    extern __shared__ __align__(16) char dsm[];
    uint32_t smbase = smem_u32(dsm);

    int bid = blockIdx.x;
    int tile = bid & 31, ks = bid >> 5;
    int gid = bid * NTHR + threadIdx.x;

    const __nv_bfloat16* B1h = g_w1_hi + (size_t)tile * 128 * KT1;
    const __nv_bfloat16* B1l = g_w1_lo + (size_t)tile * 128 * KT1;
    const __nv_bfloat16* B2h = g_w2_hi + (size_t)tile * 128 * KT2;
    const __nv_bfloat16* B2l = g_w2_lo + (size_t)tile * 128 * KT2;

    __nv_bfloat16 z16 = __float2bfloat16(0.f);
    for (int i = gid; i < BATCH * HID; i += NBLK * NTHR) {
        g_c1[i] = 0.f; g_c2[i] = 0.f;
        g_h1_hi[i] = z16; g_h1_lo[i] = z16;
        g_h2_hi[i] = z16; g_h2_lo[i] = z16;
    }
    grid_barrier();

    for (int t = 0; t < T_STEPS; t++) {
        gemm_phase_mma<1>(t, ks, tile, smbase, B1h, B1l);
        grid_barrier();
        gate_phase<1>(b1, t, gid);
        grid_barrier();
        gemm_phase_mma<2>(t, ks, tile, smbase, B2h, B2l);
        grid_barrier();
        gate_phase<2>(b2, t, gid);
        grid_barrier();
    }
}

// ---------------- epilog --------------------------------------------------------
__global__ __launch_bounds__(256) void logits_kernel(
    const float* __restrict__ W, const float* __restrict__ bias)
{
    int mt = blockIdx.x;
    __shared__ __align__(16) float As[16][128];
    __shared__ __align__(16) float Bs[16][128];
    int tid = threadIdx.x;
    int tx = tid & 15, ty = tid >> 4;
    float acc[8][8];
#pragma unroll
    for (int i = 0; i < 8; i++)
#pragma unroll
        for (int j = 0; j < 8; j++) acc[i][j] = 0.f;

    const float* Ab = g_h2all + (size_t)mt * 128 * HID;

    for (int k0 = 0; k0 < HID; k0 += 16) {
#pragma unroll
        for (int r = 0; r < 2; r++) {
            int p = tid + r * 256;
            int m = p >> 2, kq = (p & 3) * 4;
            float4 v = *(const float4*)(Ab + (size_t)m * HID + k0 + kq);
            As[kq + 0][m] = v.x; As[kq + 1][m] = v.y;
            As[kq + 2][m] = v.z; As[kq + 3][m] = v.w;
        }
#pragma unroll
        for (int r = 0; r < 2; r++) {
            int p = tid + r * 256;
            int kk = p >> 5, c4 = (p & 31) * 4;
            float4 v = *(const float4*)(W + (size_t)(k0 + kk) * DIM + c4);
            *(float4*)&Bs[kk][c4] = v;
        }
        __syncthreads();
#pragma unroll
        for (int k = 0; k < 16; k++) {
            float4 a0 = *(const float4*)&As[k][ty * 4];
            float4 a1 = *(const float4*)&As[k][ty * 4 + 64];
            float4 b0 = *(const float4*)&Bs[k][tx * 4];
            float4 b1 = *(const float4*)&Bs[k][tx * 4 + 64];
            float av[8] = {a0.x, a0.y, a0.z, a0.w, a1.x, a1.y, a1.z, a1.w};
            float bv[8] = {b0.x, b0.y, b0.z, b0.w, b1.x, b1.y, b1.z, b1.w};
#pragma unroll
            for (int i = 0; i < 8; i++)
#pragma unroll
                for (int j = 0; j < 8; j++)
                    acc[i][j] = fmaf(av[i], bv[j], acc[i][j]);
        }
        __syncthreads();
    }

#pragma unroll
    for (int i = 0; i < 8; i++) {
        int m = (i < 4) ? (ty * 4 + i) : (64 + ty * 4 + i - 4);
        float* orow = g_logits + (size_t)(mt * 128 + m) * DIM;
        int c0 = tx * 4;
        float4 o0, o1;
        o0.x = acc[i][0] + bias[c0 + 0];
        o0.y = acc[i][1] + bias[c0 + 1];
        o0.z = acc[i][2] + bias[c0 + 2];
        o0.w = acc[i][3] + bias[c0 + 3];
        o1.x = acc[i][4] + bias[c0 + 64];
        o1.y = acc[i][5] + bias[c0 + 65];
        o1.z = acc[i][6] + bias[c0 + 66];
        o1.w = acc[i][7] + bias[c0 + 67];
        *(float4*)(orow + c0) = o0;
        *(float4*)(orow + c0 + 64) = o1;
    }
}

__global__ __launch_bounds__(256) void softmax_ce_kernel(
    const int* __restrict__ tgt, float* __restrict__ probs)
{
    int warp = (blockIdx.x * blockDim.x + threadIdx.x) >> 5;
    int lane = threadIdx.x & 31;
    if (warp >= T_STEPS * BATCH) return;
    const float* row = g_logits + (size_t)warp * 128;
    float v0 = row[lane], v1 = row[lane + 32], v2 = row[lane + 64], v3 = row[lane + 96];

    float m_mel = fmaxf(v0, lane < 16 ? v1 : -1e30f);
#pragma unroll
    for (int o = 16; o; o >>= 1) m_mel = fmaxf(m_mel, __shfl_xor_sync(~0u, m_mel, o));
    float e0 = __expf(v0 - m_mel);
    float e1m = (lane < 16) ? __expf(v1 - m_mel) : 0.f;
    float s_mel = e0 + e1m;
#pragma unroll
    for (int o = 16; o; o >>= 1) s_mel += __shfl_xor_sync(~0u, s_mel, o);

    float m_har = fmaxf(fmaxf(v2, v3), lane >= 16 ? v1 : -1e30f);
#pragma unroll
    for (int o = 16; o; o >>= 1) m_har = fmaxf(m_har, __shfl_xor_sync(~0u, m_har, o));
    float e1h = (lane >= 16) ? __expf(v1 - m_har) : 0.f;
    float e2 = __expf(v2 - m_har);
    float e3 = __expf(v3 - m_har);
    float s_har = e1h + e2 + e3;
#pragma unroll
    for (int o = 16; o; o >>= 1) s_har += __shfl_xor_sync(~0u, s_har, o);

    float inv_mel = 1.0f / s_mel;
    float inv_har = 1.0f / s_har;
    float* pr = probs + (size_t)warp * 128;
    pr[lane]      = e0 * inv_mel;
    pr[lane + 32] = (lane < 16) ? e1m * inv_mel : e1h * inv_har;
    pr[lane + 64] = e2 * inv_har;
    pr[lane + 96] = e3 * inv_har;

    if (lane == 0) {
        int t0 = tgt[warp * 2 + 0];
        int t1 = tgt[warp * 2 + 1];
        t0 = min(max(t0, 0), 47);
        t1 = min(max(t1, 0), 79);
        float l0 = row[t0];
        float l1 = row[48 + t1];
        float lse_mel = m_mel + logf(s_mel);
        float lse_har = m_har + logf(s_har);
        g_lossbuf[warp] = 0.5f * (lse_mel - l0) + 0.5f * (lse_har - l1);
    }
}

__global__ __launch_bounds__(256) void loss_reduce_kernel(float* __restrict__ out)
{
    __shared__ float sm[256];
    float s = 0.f;
    for (int i = threadIdx.x; i < T_STEPS * BATCH; i += 256) s += g_lossbuf[i];
    sm[threadIdx.x] = s;
    __syncthreads();
    for (int o = 128; o; o >>= 1) {
        if (threadIdx.x < o) sm[threadIdx.x] += sm[threadIdx.x + o];
        __syncthreads();
    }
    if (threadIdx.x == 0)
        out[0] = sm[0] / (float)(T_STEPS * BATCH);
}

// ---------------- launch --------------------------------------------------------
extern "C" void kernel_launch(void* const* d_in, const int* in_sizes, int n_in,
                              void* d_out, int out_size)
{
    const float* inSeq = (const float*)d_in[0];
    const int*   tgt   = (const int*)d_in[1];
    const float* W1    = (const float*)d_in[2];
    const float* b1    = (const float*)d_in[3];
    const float* W2    = (const float*)d_in[4];
    const float* b2    = (const float*)d_in[5];
    const float* outW  = (const float*)d_in[6];
    const float* outB  = (const float*)d_in[7];
    float* out = (float*)d_out;

    cudaFuncSetAttribute(lstm_mma_kernel,
                         cudaFuncAttributeMaxDynamicSharedMemorySize, DSMEM_B);

    conv_x_kernel<<<(T_STEPS * BATCH * DIM) / 256, 256>>>(inSeq);
    conv_w1_kernel<<<(int)(((size_t)KT1 * G4 + 255) / 256), 256>>>(W1);
    conv_w2_kernel<<<(int)(((size_t)KT2 * G4 + 255) / 256), 256>>>(W2);

    lstm_mma_kernel<<<NBLK, NTHR, DSMEM_B>>>(b1, b2);

    logits_kernel<<<(T_STEPS * BATCH) / 128, 256>>>(outW, outB);
    softmax_ce_kernel<<<(T_STEPS * BATCH * 32) / 256, 256>>>(tgt, out);
    loss_reduce_kernel<<<1, 256>>>(out + (out_size - 1));
}